// round 14
// baseline (speedup 1.0000x reference)
#include <cuda_runtime.h>
#include <cuda_fp16.h>
#include <math.h>
#include <stdint.h>

// Problem constants
#define BB   2048
#define TT   32
#define BT   65536        // BB*TT
#define DIN_ 1024
#define DH_  64
#define HH   512
#define G4   2048         // 4*H
#define KIN  576          // DH + H
#define AA   64

typedef unsigned long long u64;

#define SW128(off) ((off) ^ (((off) >> 3) & 0x70))

// ======================= helpers =======================
__device__ __forceinline__ uint32_t smem_to_u32(const void* p) {
    uint32_t a;
    asm("{ .reg .u64 t; cvta.to.shared.u64 t, %1; cvt.u32.u64 %0, t; }" : "=r"(a) : "l"(p));
    return a;
}
__device__ __forceinline__ void cpa16(uint32_t s, const void* g) {
    asm volatile("cp.async.cg.shared.global [%0], [%1], 16;" :: "r"(s), "l"(g));
}
#define CP_COMMIT() asm volatile("cp.async.commit_group;" ::: "memory")
#define CP_WAIT(n)  asm volatile("cp.async.wait_group %0;" :: "n"(n) : "memory")
__device__ __forceinline__ void ldsm4(uint32_t* r, uint32_t addr) {
    asm volatile("ldmatrix.sync.aligned.m8n8.x4.shared.b16 {%0,%1,%2,%3}, [%4];"
        : "=r"(r[0]), "=r"(r[1]), "=r"(r[2]), "=r"(r[3]) : "r"(addr));
}
__device__ __forceinline__ void mma16816h(float* c, const uint32_t* a, const uint32_t* b) {
    asm volatile("mma.sync.aligned.m16n8k16.row.col.f32.f16.f16.f32 "
        "{%0,%1,%2,%3}, {%4,%5,%6,%7}, {%8,%9}, {%0,%1,%2,%3};"
        : "+f"(c[0]), "+f"(c[1]), "+f"(c[2]), "+f"(c[3])
        : "r"(a[0]), "r"(a[1]), "r"(a[2]), "r"(a[3]), "r"(b[0]), "r"(b[1]));
}
__device__ __forceinline__ u64 pkh4(float a, float b, float c, float d) {
    __half2 lo = __floats2half2_rn(a, b);
    __half2 hi = __floats2half2_rn(c, d);
    u64 r;
    asm("mov.b64 %0, {%1, %2};" : "=l"(r) : "r"(*(uint32_t*)&lo), "r"(*(uint32_t*)&hi));
    return r;
}
// fast gates
__device__ __forceinline__ float tapx(float x) {
    float y; asm("tanh.approx.f32 %0, %1;" : "=f"(y) : "f"(x)); return y;
}
__device__ __forceinline__ float sigax(float x) { return fmaf(tapx(0.5f * x), 0.5f, 0.5f); }
// accurate-ish tanh for final output
__device__ __forceinline__ float ftanh(float x) { return 1.f - __fdividef(2.f, __expf(2.f * x) + 1.f); }

// ======================= scratch (device globals) =======================
__device__ __half g_xph[BT * DH_];               // x (fp16)  [(b*T+t)*64+d]
__device__ __half g_wph[2][8][256 * 576];        // LSTM W [dir][nb][n'(256)*576+k], n'=nl*4+gate
__device__ __half g_wdh[64 * 1024];              // Wd^T  [n(64)][k(1024)]
__device__ __half g_wch[64 * 1024];              // Wc^T  [a(64)][h(1024)]
__device__ __half g_hh[2][2][BB * HH];           // [dir][buf][slot*512+n]  (PHYSICAL slot index)
__device__ __half g_hcatH[BT * 2 * HH];          // [b][t][1024] masked, bw at reversed t
__device__ float g_mu3[BB];
__device__ float g_rs3[BB];
__device__ int   g_pau[BB];                      // (au<<16)|row, sorted desc by au
__device__ int   g_blkmax[16];                   // max au per 128-row block
__device__ unsigned g_bar[32];                   // group barriers, zero-init

__device__ __forceinline__ void bar_arrive_release(unsigned* addr) {
    asm volatile("red.release.gpu.global.add.u32 [%0], 1;" :: "l"(addr) : "memory");
}
__device__ __forceinline__ unsigned bar_ld_acquire(unsigned* addr) {
    unsigned v;
    asm volatile("ld.acquire.gpu.global.u32 %0, [%1];" : "=r"(v) : "l"(addr) : "memory");
    return v;
}

// ---------------- KS: counting sort of batch rows by au (descending) ----------------
__global__ void ks_sort(const int* __restrict__ au) {
    __shared__ int cnt[33], off[33];
    int tid = threadIdx.x;
    if (tid < 33) cnt[tid] = 0;
    __syncthreads();
    for (int r = tid; r < BB; r += 256) atomicAdd(&cnt[au[r]], 1);
    __syncthreads();
    if (tid == 0) {
        int acc = 0;
        for (int v = 32; v >= 1; v--) { off[v] = acc; acc += cnt[v]; }
    }
    __syncthreads();
    if (tid < 33) cnt[tid] = 0;
    __syncthreads();
    for (int r = tid; r < BB; r += 256) {
        int a = au[r];
        int pos = off[a] + atomicAdd(&cnt[a], 1);
        g_pau[pos] = (a << 16) | r;
    }
    __syncthreads();
    if (tid < 16) g_blkmax[tid] = g_pau[tid * 128] >> 16;
}

// ---------------- KP: prepack LSTM W into fp16, gate-interleaved, K-major ----------------
__global__ void kp_w(const float* __restrict__ Wfw, const float* __restrict__ Wbw) {
    int idx = blockIdx.x * 256 + threadIdx.x;    // 2 * 576 * 2048 total
    int dir = idx >= (KIN * G4);
    int r = idx - dir * (KIN * G4);
    int k = r >> 11;
    int col = r & 2047;
    const float* W = dir ? Wbw : Wfw;
    float v = W[(size_t)k * G4 + col];
    int g = col >> 9, rr = col & 511, nb = rr >> 6, nl = rr & 63;
    int np = nl * 4 + g;
    g_wph[dir][nb][np * 576 + k] = __float2half(v);
}

// ---------------- KP2: transpose-pack Wd and Wc to fp16 [n][k] ----------------
__global__ void kp_dc(const float* __restrict__ Wd, const float* __restrict__ Wc) {
    int idx = blockIdx.x * 256 + threadIdx.x;    // 2 * 65536
    int which = idx >= 65536;
    int r = idx & 65535;
    int k = r >> 6, n = r & 63;
    if (!which) g_wdh[n * 1024 + k] = __float2half(Wd[(size_t)k * 64 + n]);
    else        g_wch[n * 1024 + k] = __float2half(Wc[(size_t)k * 64 + n]);
}

// ---------------- K1: LN1-stats (fused) -> LN1 -> dense(HMMA) -> LN2 -> relu -> fp16 ----------------
__global__ void __launch_bounds__(256)
k1_dense(const float* __restrict__ ud,
         const float* __restrict__ g1, const float* __restrict__ b1,
         const float* __restrict__ bd,
         const float* __restrict__ g2, const float* __restrict__ b2) {
    __shared__ __align__(16) char sm1[33792];    // A 16K | B 2x8K ; buf f32[128][65] aliases
    __shared__ float g1s[1024], b1s[1024];
    __shared__ float smu[128], srs[128];
    uint32_t s32 = smem_to_u32(sm1);
    float* buf = (float*)sm1;

    int tid = threadIdx.x;
    int wid = tid >> 5, lid = tid & 31;
    int bx = blockIdx.x;
    int wm = wid & 3, wn = wid >> 2;
    int l2 = lid & 3;

    #pragma unroll
    for (int i = 0; i < 4; i++) { g1s[tid + i * 256] = g1[tid + i * 256]; b1s[tid + i * 256] = b1[tid + i * 256]; }

    // ---- pass 1: LN1 stats, 16 lanes per row, 8 rows per thread ----
    int rowL = tid >> 4, cl = tid & 15;
    float mus[8], rss[8];
    #pragma unroll 1
    for (int it = 0; it < 8; it++) {
        int r = rowL + it * 16;
        const float4* p = (const float4*)(ud + (size_t)(bx * 128 + r) * DIN_) + cl;
        float s = 0.f, q = 0.f;
        #pragma unroll
        for (int c = 0; c < 16; c++) {
            float4 v = p[c * 16];
            s += v.x + v.y + v.z + v.w;
            q += v.x * v.x + v.y * v.y + v.z * v.z + v.w * v.w;
        }
        #pragma unroll
        for (int o = 1; o < 16; o <<= 1) {
            s += __shfl_xor_sync(0xffffffffu, s, o);
            q += __shfl_xor_sync(0xffffffffu, q, o);
        }
        float mu = s / 1024.f;
        mus[it] = mu;
        rss[it] = rsqrtf(q / 1024.f - mu * mu + 1e-12f);
    }
    __syncthreads();

    uint32_t aSts[8];
    #pragma unroll
    for (int it = 0; it < 8; it++)
        aSts[it] = SW128((uint32_t)((rowL + it * 16) * 128 + cl * 8));

    uint32_t swB[2]; int bofs[2];
    #pragma unroll
    for (int i = 0; i < 2; i++) {
        int idx = tid + i * 256;
        int row = idx >> 3, q = idx & 7;
        swB[i] = SW128((uint32_t)(row * 128 + q * 16));
        bofs[i] = row * 1024 + q * 8;
    }

    int lar = (lid & 7) + ((lid >> 3) & 1) * 8;
    int lac2 = ((lid >> 4) & 1) * 16;
    int lbr = (lid & 7) + ((lid >> 4) & 1) * 8;
    int lbc2 = ((lid >> 3) & 1) * 16;
    uint32_t aBase[2], aXor[2], bBase[2], bXor[2];
    #pragma unroll
    for (int mt = 0; mt < 2; mt++) {
        int r = wm * 32 + mt * 16 + lar;
        aBase[mt] = (uint32_t)(r * 128);
        aXor[mt] = (uint32_t)((r & 7) << 4);
    }
    #pragma unroll
    for (int np = 0; np < 2; np++) {
        int r = wn * 32 + np * 16 + lbr;
        bBase[np] = (uint32_t)(r * 128);
        bXor[np] = (uint32_t)((r & 7) << 4);
    }

    float acc[2][4][4];
    #pragma unroll
    for (int mt = 0; mt < 2; mt++)
        #pragma unroll
        for (int nt = 0; nt < 4; nt++)
            #pragma unroll
            for (int j = 0; j < 4; j++) acc[mt][nt][j] = 0.f;

    u64 regA[8];
    auto doLoadA = [&](int kc) {
        float4 gg = *(const float4*)&g1s[kc * 64 + cl * 4];
        float4 bbv = *(const float4*)&b1s[kc * 64 + cl * 4];
        #pragma unroll
        for (int it = 0; it < 8; it++) {
            int r = rowL + it * 16;
            float4 v = *(const float4*)(ud + (size_t)(bx * 128 + r) * DIN_ + kc * 64 + cl * 4);
            float mu = mus[it], rs = rss[it];
            regA[it] = pkh4((v.x - mu) * rs * gg.x + bbv.x,
                            (v.y - mu) * rs * gg.y + bbv.y,
                            (v.z - mu) * rs * gg.z + bbv.z,
                            (v.w - mu) * rs * gg.w + bbv.w);
        }
    };
    auto doStsA = [&]() {
        #pragma unroll
        for (int it = 0; it < 8; it++)
            *(u64*)(sm1 + aSts[it]) = regA[it];
    };
    auto doCpaB = [&](int kc, int st) {
        uint32_t sb = s32 + 16384 + (uint32_t)st * 8192u;
        #pragma unroll
        for (int i = 0; i < 2; i++)
            cpa16(sb + swB[i], g_wdh + bofs[i] + kc * 64);
        CP_COMMIT();
    };

    doLoadA(0);
    doCpaB(0, 0);
    int st = 0;

    #pragma unroll 1
    for (int kc = 0; kc < 16; kc++) {
        __syncthreads();
        if (kc < 15) doCpaB(kc + 1, st ^ 1);
        if (kc < 15) { CP_WAIT(1); } else { CP_WAIT(0); }
        doStsA();
        if (kc < 15) doLoadA(kc + 1);
        __syncthreads();

        uint32_t bS = s32 + 16384 + (uint32_t)st * 8192u;
        #pragma unroll
        for (int kt = 0; kt < 4; kt++) {
            uint32_t ah[2][4], bf[2][4];
            #pragma unroll
            for (int mt = 0; mt < 2; mt++) {
                uint32_t cb = ((uint32_t)(kt * 32 + lac2)) ^ aXor[mt];
                ldsm4(ah[mt], s32 + aBase[mt] + cb);
            }
            #pragma unroll
            for (int np = 0; np < 2; np++) {
                uint32_t cb = ((uint32_t)(kt * 32 + lbc2)) ^ bXor[np];
                ldsm4(bf[np], bS + bBase[np] + cb);
            }
            #pragma unroll
            for (int mt = 0; mt < 2; mt++)
                #pragma unroll
                for (int nt = 0; nt < 4; nt++)
                    mma16816h(acc[mt][nt], ah[mt], &bf[nt >> 1][(nt & 1) * 2]);
        }
        st ^= 1;
    }

    __syncthreads();   // all MMA done; smem now reused as buf

    #pragma unroll
    for (int mt = 0; mt < 2; mt++) {
        int r = wm * 32 + mt * 16 + (lid >> 2);
        #pragma unroll
        for (int nt = 0; nt < 4; nt++) {
            int c = wn * 32 + nt * 8 + l2 * 2;
            float b0 = bd[c], b1v = bd[c + 1];
            buf[r * 65 + c]           = acc[mt][nt][0] + b0;
            buf[r * 65 + c + 1]       = acc[mt][nt][1] + b1v;
            buf[(r + 8) * 65 + c]     = acc[mt][nt][2] + b0;
            buf[(r + 8) * 65 + c + 1] = acc[mt][nt][3] + b1v;
        }
    }
    __syncthreads();

    if (tid < 128) {
        float s = 0.f, q = 0.f;
        #pragma unroll
        for (int c = 0; c < 64; c++) { float v = buf[tid * 65 + c]; s += v; q += v * v; }
        float mu = s / 64.f;
        smu[tid] = mu;
        srs[tid] = rsqrtf(q / 64.f - mu * mu + 1e-12f);
    }
    __syncthreads();

    int ty = tid >> 4, tx = tid & 15;
    #pragma unroll
    for (int r = 0; r < 8; r++) {
        int lr = ty * 8 + r;
        float mu = smu[lr], rs = srs[lr];
        int gr = bx * 128 + lr;
        #pragma unroll
        for (int j = 0; j < 4; j++) {
            int c = tx * 4 + j;
            float y = (buf[lr * 65 + c] - mu) * rs * g2[c] + b2[c];
            g_xph[(size_t)gr * DH_ + c] = __float2half(fmaxf(y, 0.f));
        }
    }
}

// ---------------- K2P: persistent bidirectional LSTM (sorted rows, early-exit) ----------------
// grid (16 Mblk, 4 nbPair, 2 dir) = 128 CTAs, 256 threads (8 warps: 2m x 4n).
// Rows permuted by au-descending sort; group runs only Tact = blkmax[bx] steps.
__global__ void __launch_bounds__(256, 1)
k2p_persist(const float* __restrict__ bfw, const float* __restrict__ bbw,
            const int* __restrict__ au) {
    extern __shared__ __align__(16) char dsm[];

    int tid = threadIdx.x;
    int wid = tid >> 5, lid = tid & 31;
    int bx = blockIdx.x, npair = blockIdx.y, dir = blockIdx.z;
    int wm = wid >> 2, wn = wid & 3;          // warp grid 2m x 4n
    int grp = dir * 16 + bx;

    uint32_t b32 = smem_to_u32(dsm);
    uint32_t tb32 = (b32 + 1023) & ~1023u;
    char* tb = dsm + (tb32 - b32);
    float* cS = (float*)(tb + 147456);            // c-state [128][129] f32
    char*  hst = tb + 147456 + 66048;             // h-stage [128][68] fp16

    const float* bias = dir ? bbw : bfw;
    int Tact = g_blkmax[bx];

    // ---- cp.async invariants: A (4 units/thread), B (8 units/thread) ----
    uint32_t swA[4]; int gbA[4], aA[4], hbA[4], qA8[4];
    #pragma unroll
    for (int i = 0; i < 4; i++) {
        int idx = tid + i * 256;
        int row = idx >> 3, q = idx & 7;
        swA[i] = SW128((uint32_t)(row * 128 + q * 16));
        qA8[i] = q * 8;
        int p = g_pau[bx * 128 + row];
        gbA[i] = p & 0xFFFF;                  // logical batch row (for x)
        aA[i]  = p >> 16;                     // au
        hbA[i] = (bx * 128 + row) * HH + q * 8;   // PHYSICAL slot base (for h)
    }
    uint32_t swB[8]; int boff[8];
    #pragma unroll
    for (int i = 0; i < 8; i++) {
        int idx = tid + i * 256;
        int row = idx >> 3, q = idx & 7;
        swB[i] = SW128((uint32_t)(row * 128 + q * 16));
        boff[i] = row * KIN + q * 8;
    }

    // ---- ldsm invariants ----
    int lar = (lid & 7) + ((lid >> 3) & 1) * 8;
    int lac2 = ((lid >> 4) & 1) * 16;
    int lbr = (lid & 7) + ((lid >> 4) & 1) * 8;
    int lbc2 = ((lid >> 3) & 1) * 16;
    uint32_t aBase[4], aXor[4], bBase[4], bXor[4];
    #pragma unroll
    for (int mt = 0; mt < 4; mt++) {
        int r = wm * 64 + mt * 16 + lar;
        aBase[mt] = (uint32_t)(r * 128);
        aXor[mt] = (uint32_t)((r & 7) << 4);
    }
    #pragma unroll
    for (int np = 0; np < 4; np++) {
        int r = wn * 64 + np * 16 + lbr;
        bBase[np] = (uint32_t)(r * 128);
        bXor[np] = (uint32_t)((r & 7) << 4);
    }

    int l2 = lid & 3;
    int erow[4];
    #pragma unroll
    for (int mt = 0; mt < 4; mt++)
        erow[mt] = wm * 64 + mt * 16 + (lid >> 2) + (l2 & 1) * 8;

    float acc[4][8][4];
    #pragma unroll
    for (int mt = 0; mt < 4; mt++)
        #pragma unroll
        for (int nt = 0; nt < 8; nt++)
            #pragma unroll
            for (int j = 0; j < 4; j++) acc[mt][nt][j] = 0.f;

    int sbuf = 0, cbuf = 0;

    auto issueC = [&](int t, int ci) {
        int NC = (t == 0) ? 1 : 9;
        int half = (ci >= NC) ? 1 : 0;
        int kc = ci - half * NC;
        uint32_t sb = tb32 + (uint32_t)sbuf * 49152u;
        if (kc == 0) {
            #pragma unroll
            for (int i = 0; i < 4; i++) {
                int ts = t;
                if (dir) ts = (t < aA[i]) ? (aA[i] - 1 - t) : t;
                cpa16(sb + swA[i], g_xph + (gbA[i] * TT + ts) * DH_ + qA8[i]);
            }
        } else {
            const __half* hp = g_hh[dir][(t & 1) ^ 1];
            int e0 = (kc - 1) * 64;
            #pragma unroll
            for (int i = 0; i < 4; i++)
                cpa16(sb + swA[i], hp + hbA[i] + e0);
        }
        int nb = npair * 2 + half;
        const __half* wp = g_wph[dir][nb];
        int ke = kc * 64;
        #pragma unroll
        for (int i = 0; i < 8; i++)
            cpa16(sb + 16384 + swB[i], wp + boff[i] + ke);
        CP_COMMIT();
        sbuf = (sbuf == 2) ? 0 : sbuf + 1;
    };

    int pending = 0;

    #pragma unroll 1
    for (int t = 0; t < Tact; t++) {
        int NC = (t == 0) ? 1 : 9;
        int NC2 = 2 * NC;

        int issued = pending;
        while (issued < NC2 && issued < 2) { issueC(t, issued); issued++; }

        #pragma unroll 1
        for (int ci = 0; ci < NC2; ci++) {
            if (issued - ci >= 2) CP_WAIT(1);
            else                  CP_WAIT(0);
            __syncthreads();
            if (issued < NC2) { issueC(t, issued); issued++; }

            uint32_t sb = tb32 + (uint32_t)cbuf * 49152u;
            cbuf = (cbuf == 2) ? 0 : cbuf + 1;

            #pragma unroll
            for (int kt = 0; kt < 4; kt++) {
                uint32_t ah[4][4], bf[4][4];
                #pragma unroll
                for (int mt = 0; mt < 4; mt++) {
                    uint32_t cb = ((uint32_t)(kt * 32 + lac2)) ^ aXor[mt];
                    ldsm4(ah[mt], sb + aBase[mt] + cb);
                }
                #pragma unroll
                for (int np = 0; np < 4; np++) {
                    uint32_t cb = ((uint32_t)(kt * 32 + lbc2)) ^ bXor[np];
                    ldsm4(bf[np], sb + 16384 + bBase[np] + cb);
                }
                #pragma unroll
                for (int mt = 0; mt < 4; mt++)
                    #pragma unroll
                    for (int nt = 0; nt < 8; nt++)
                        mma16816h(acc[mt][nt], ah[mt], &bf[nt >> 1][(nt & 1) * 2]);
            }

            if (ci == NC - 1 || ci == NC2 - 1) {
                int half = (ci >= NC) ? 1 : 0;
                int nb = npair * 2 + half;
                bool oddl = (l2 & 1);
                #pragma unroll
                for (int mt = 0; mt < 4; mt++) {
                    int row = erow[mt];
                    #pragma unroll
                    for (int nt = 0; nt < 8; nt++) {
                        float o0 = acc[mt][nt][0], o1 = acc[mt][nt][1];
                        float o2 = acc[mt][nt][2], o3 = acc[mt][nt][3];
                        float r0 = __shfl_xor_sync(0xffffffffu, o0, 1);
                        float r1 = __shfl_xor_sync(0xffffffffu, o1, 1);
                        float r2 = __shfl_xor_sync(0xffffffffu, o2, 1);
                        float r3 = __shfl_xor_sync(0xffffffffu, o3, 1);
                        float zi, zj, zf, zo;
                        if (!oddl) { zi = o0; zj = o1; zf = r0; zo = r1; }
                        else       { zi = r2; zj = r3; zf = o2; zo = o3; }
                        int u = wn * 16 + nt * 2 + (l2 >> 1);
                        int n = nb * 64 + u;
                        float vi = zi + bias[n];
                        float vj = zj + bias[HH + n];
                        float vf = zf + bias[2 * HH + n];
                        float vo = zo + bias[3 * HH + n];
                        int cidx = row * 129 + half * 64 + u;
                        float cp = (t == 0) ? 0.f : cS[cidx];
                        float cn = cp * sigax(vf + 1.0f) + sigax(vi) * tapx(vj);
                        float hn = tapx(cn) * sigax(vo);
                        cS[cidx] = cn;
                        *(__half*)(hst + (row * 68 + u) * 2) = __float2half(hn);
                    }
                }
                #pragma unroll
                for (int mt = 0; mt < 4; mt++)
                    #pragma unroll
                    for (int nt = 0; nt < 8; nt++)
                        #pragma unroll
                        for (int j = 0; j < 4; j++) acc[mt][nt][j] = 0.f;

                __syncthreads();
                // coalesced copy h-stage -> g_hh (PHYSICAL slots, for recurrence)
                __half* oh = g_hh[dir][t & 1];
                #pragma unroll
                for (int i = 0; i < 8; i++) {
                    int idx = tid + i * 256;
                    int row = idx >> 4, ch = idx & 15;
                    u64 v = *(const u64*)(hst + row * 136 + ch * 8);
                    *(u64*)((char*)oh + ((size_t)(bx * 128 + row) * HH + nb * 64 + ch * 4) * 2) = v;
                }
                // masked (+ reversed for bw) copy -> g_hcatH fp16 [b][t][1024] (LOGICAL rows)
                #pragma unroll
                for (int i = 0; i < 8; i++) {
                    int idx = tid + i * 256;
                    int row = idx >> 4, ch = idx & 15;
                    int p = g_pau[bx * 128 + row];
                    int gb = p & 0xFFFF;
                    int a0 = p >> 16;
                    u64 v = *(const u64*)(hst + row * 136 + ch * 8);
                    int ts;
                    if (t < a0) ts = dir ? (a0 - 1 - t) : t;
                    else { ts = t; v = 0ull; }
                    *(u64*)((char*)g_hcatH +
                        (((size_t)gb * TT + ts) * (2 * HH) + dir * HH + nb * 64 + ch * 4) * 2) = v;
                }
            }
        }

        if (t < Tact - 1) {
            issueC(t + 1, 0);
            pending = 1;
            __syncthreads();
            if (tid == 0) {
                bar_arrive_release(&g_bar[grp]);
                unsigned target = 4u * (unsigned)(t + 1);
                while (bar_ld_acquire(&g_bar[grp]) < target) __nanosleep(64);
            }
            __syncthreads();
        }
    }

    // final arrival + reset for graph-replay determinism (target = 4*Tact for this group)
    __syncthreads();
    if (tid == 0) {
        bar_arrive_release(&g_bar[grp]);
        if (npair == 0) {
            while (bar_ld_acquire(&g_bar[grp]) < 4u * (unsigned)Tact) __nanosleep(64);
            g_bar[grp] = 0u;
            __threadfence();
        }
    }

    // ---- tail: zero-fill hcat for fully-masked steps (ts = t, all rows masked) ----
    #pragma unroll 1
    for (int t = Tact; t < TT; t++) {
        #pragma unroll
        for (int i = 0; i < 16; i++) {
            int idx = tid + i * 256;
            int row = idx >> 5, ch = idx & 31;
            int p = g_pau[bx * 128 + row];
            int gb = p & 0xFFFF;
            *(u64*)((char*)g_hcatH +
                (((size_t)gb * TT + t) * (2 * HH) + dir * HH + npair * 128 + ch * 4) * 2) = 0ull;
        }
    }
}

// ---------------- K3: per-batch LN3 stats over contiguous fp16 [b][32768] ----------------
__global__ void k3_stats() {
    __shared__ float ssum[256], ssq[256];
    int b = blockIdx.x, tid = threadIdx.x;
    const uint4* p = (const uint4*)(g_hcatH + (size_t)b * (TT * 2 * HH));
    float s = 0.f, q = 0.f;
    #pragma unroll 4
    for (int i = 0; i < 16; i++) {
        uint4 v = p[tid + i * 256];
        const __half* hv = (const __half*)&v;
        #pragma unroll
        for (int e = 0; e < 8; e++) {
            float f = __half2float(hv[e]);
            s += f; q += f * f;
        }
    }
    ssum[tid] = s; ssq[tid] = q;
    __syncthreads();
    for (int o = 128; o; o >>= 1) {
        if (tid < o) { ssum[tid] += ssum[tid + o]; ssq[tid] += ssq[tid + o]; }
        __syncthreads();
    }
    if (tid == 0) {
        float mu = ssum[0] / 32768.f;
        g_mu3[b] = mu;
        g_rs3[b] = rsqrtf(ssq[0] / 32768.f - mu * mu + 1e-12f);
    }
}

// ---------------- K4: relu(LN3) -> conv(HMMA) -> +bc -> tanh -> out ----------------
__global__ void __launch_bounds__(256)
k4_out(const float* __restrict__ g3, const float* __restrict__ b3,
       const float* __restrict__ bc, float* __restrict__ out) {
    __shared__ __align__(16) char sm4[32768];    // A 16K | B 2x8K
    __shared__ float g3s[1024], b3s[1024];
    uint32_t s32 = smem_to_u32(sm4);

    int tid = threadIdx.x;
    int wid = tid >> 5, lid = tid & 31;
    int bx = blockIdx.x;
    int wm = wid & 3, wn = wid >> 2;
    int l2 = lid & 3;

    #pragma unroll
    for (int i = 0; i < 4; i++) { g3s[tid + i * 256] = g3[tid + i * 256]; b3s[tid + i * 256] = b3[tid + i * 256]; }

    int rowL = tid >> 3, cl = tid & 7;
    float amus[4], arss[4];
    uint32_t aSts[4];
    #pragma unroll
    for (int it = 0; it < 4; it++) {
        int r = rowL + it * 32;
        int bat = (bx * 128 + r) >> 5;
        amus[it] = g_mu3[bat];
        arss[it] = g_rs3[bat];
        aSts[it] = SW128((uint32_t)(r * 128 + cl * 16));
    }
    __syncthreads();

    uint32_t swB[2]; int bofs[2];
    #pragma unroll
    for (int i = 0; i < 2; i++) {
        int idx = tid + i * 256;
        int row = idx >> 3, q = idx & 7;
        swB[i] = SW128((uint32_t)(row * 128 + q * 16));
        bofs[i] = row * 1024 + q * 8;
    }

    int lar = (lid & 7) + ((lid >> 3) & 1) * 8;
    int lac2 = ((lid >> 4) & 1) * 16;
    int lbr = (lid & 7) + ((lid >> 4) & 1) * 8;
    int lbc2 = ((lid >> 3) & 1) * 16;
    uint32_t aBase[2], aXor[2], bBase[2], bXor[2];
    #pragma unroll
    for (int mt = 0; mt < 2; mt++) {
        int r = wm * 32 + mt * 16 + lar;
        aBase[mt] = (uint32_t)(r * 128);
        aXor[mt] = (uint32_t)((r & 7) << 4);
    }
    #pragma unroll
    for (int np = 0; np < 2; np++) {
        int r = wn * 32 + np * 16 + lbr;
        bBase[np] = (uint32_t)(r * 128);
        bXor[np] = (uint32_t)((r & 7) << 4);
    }

    float acc[2][4][4];
    #pragma unroll
    for (int mt = 0; mt < 2; mt++)
        #pragma unroll
        for (int nt = 0; nt < 4; nt++)
            #pragma unroll
            for (int j = 0; j < 4; j++) acc[mt][nt][j] = 0.f;

    uint4 regA[4];
    auto doLoadA = [&](int kc) {
        float4 gg0 = *(const float4*)&g3s[kc * 64 + cl * 8];
        float4 gg1 = *(const float4*)&g3s[kc * 64 + cl * 8 + 4];
        float4 bb0 = *(const float4*)&b3s[kc * 64 + cl * 8];
        float4 bb1 = *(const float4*)&b3s[kc * 64 + cl * 8 + 4];
        #pragma unroll
        for (int it = 0; it < 4; it++) {
            int r = rowL + it * 32;
            uint4 v = *(const uint4*)(g_hcatH + (size_t)(bx * 128 + r) * (2 * HH) + kc * 64 + cl * 8);
            const __half* hv = (const __half*)&v;
            float amu = amus[it], ars = arss[it];
            uint4 o;
            __half* ho = (__half*)&o;
            ho[0] = __float2half(fmaxf((__half2float(hv[0]) - amu) * ars * gg0.x + bb0.x, 0.f));
            ho[1] = __float2half(fmaxf((__half2float(hv[1]) - amu) * ars * gg0.y + bb0.y, 0.f));
            ho[2] = __float2half(fmaxf((__half2float(hv[2]) - amu) * ars * gg0.z + bb0.z, 0.f));
            ho[3] = __float2half(fmaxf((__half2float(hv[3]) - amu) * ars * gg0.w + bb0.w, 0.f));
            ho[4] = __float2half(fmaxf((__half2float(hv[4]) - amu) * ars * gg1.x + bb1.x, 0.f));
            ho[5] = __float2half(fmaxf((__half2float(hv[5]) - amu) * ars * gg1.y + bb1.y, 0.f));
            ho[6] = __float2half(fmaxf((__half2float(hv[6]) - amu) * ars * gg1.z + bb1.z, 0.f));
            ho[7] = __float2half(fmaxf((__half2float(hv[7]) - amu) * ars * gg1.w + bb1.w, 0.f));
            regA[it] = o;
        }
    };
    auto doStsA = [&]() {
        #pragma unroll
        for (int it = 0; it < 4; it++)
            *(uint4*)(sm4 + aSts[it]) = regA[it];
    };
    auto doCpaB = [&](int kc, int st) {
        uint32_t sb = s32 + 16384 + (uint32_t)st * 8192u;
        #pragma unroll
        for (int i = 0; i < 2; i++)
            cpa16(sb + swB[i], g_wch + bofs[i] + kc * 64);
        CP_COMMIT();
    };

    doLoadA(0);
    doCpaB(0, 0);
    int st = 0;

    #pragma unroll 1
    for (int kc = 0; kc < 16; kc++) {
        __syncthreads();
        if (kc < 15) doCpaB(kc + 1, st ^ 1);
        if (kc < 15) { CP_WAIT(1); } else { CP_WAIT(0); }
        doStsA();
        if (kc < 15) doLoadA(kc + 1);
        __syncthreads();

        uint32_t bS = s32 + 16384 + (uint32_t)st * 8192u;
        #pragma unroll
        for (int kt = 0; kt < 4; kt++) {
            uint32_t ah[2][4], bf[2][4];
            #pragma unroll
            for (int mt = 0; mt < 2; mt++) {
                uint32_t cb = ((uint32_t)(kt * 32 + lac2)) ^ aXor[mt];
                ldsm4(ah[mt], s32 + aBase[mt] + cb);
            }
            #pragma unroll
            for (int np = 0; np < 2; np++) {
                uint32_t cb = ((uint32_t)(kt * 32 + lbc2)) ^ bXor[np];
                ldsm4(bf[np], bS + bBase[np] + cb);
            }
            #pragma unroll
            for (int mt = 0; mt < 2; mt++)
                #pragma unroll
                for (int nt = 0; nt < 4; nt++)
                    mma16816h(acc[mt][nt], ah[mt], &bf[nt >> 1][(nt & 1) * 2]);
        }
        st ^= 1;
    }

    #pragma unroll
    for (int mt = 0; mt < 2; mt++) {
        int r = wm * 32 + mt * 16 + (lid >> 2);
        int gr = bx * 128 + r;
        #pragma unroll
        for (int nt = 0; nt < 4; nt++) {
            int c = wn * 32 + nt * 8 + l2 * 2;
            float b0 = bc[c], b1v = bc[c + 1];
            float2 v0 = make_float2(ftanh(acc[mt][nt][0] + b0), ftanh(acc[mt][nt][1] + b1v));
            float2 v1 = make_float2(ftanh(acc[mt][nt][2] + b0), ftanh(acc[mt][nt][3] + b1v));
            *(float2*)(out + (size_t)gr * AA + c) = v0;
            *(float2*)(out + (size_t)(gr + 8) * AA + c) = v1;
        }
    }
}

// ---------------- launch ----------------
extern "C" void kernel_launch(void* const* d_in, const int* in_sizes, int n_in,
                              void* d_out, int out_size) {
    int s = (n_in >= 18) ? 1 : 0;
    const float* ud  = (const float*)d_in[0];
    const int*   au  = (const int*)  d_in[2];
    const float* g1  = (const float*)d_in[3 + s];
    const float* b1  = (const float*)d_in[4 + s];
    const float* Wd  = (const float*)d_in[5 + s];
    const float* bd  = (const float*)d_in[6 + s];
    const float* g2  = (const float*)d_in[7 + s];
    const float* b2  = (const float*)d_in[8 + s];
    const float* Wfw = (const float*)d_in[9 + s];
    const float* bfw = (const float*)d_in[10 + s];
    const float* Wbw = (const float*)d_in[11 + s];
    const float* bbw = (const float*)d_in[12 + s];
    const float* g3  = (const float*)d_in[13 + s];
    const float* b3  = (const float*)d_in[14 + s];
    const float* Wc  = (const float*)d_in[15 + s];
    const float* bc  = (const float*)d_in[16 + s];
    float* out = (float*)d_out;

    const int K2_SMEM = 1024 + 3 * 49152 + 66048 + 17408;   // 231936 bytes
    cudaFuncSetAttribute(k2p_persist, cudaFuncAttributeMaxDynamicSharedMemorySize, K2_SMEM);

    ks_sort<<<1, 256>>>(au);
    kp_w<<<(2 * KIN * G4) / 256, 256>>>(Wfw, Wbw);
    kp_dc<<<512, 256>>>(Wd, Wc);
    k1_dense<<<BT / 128, 256>>>(ud, g1, b1, bd, g2, b2);
    k2p_persist<<<dim3(16, 4, 2), 256, K2_SMEM>>>(bfw, bbw, au);
    k3_stats<<<BB, 256>>>();
    k4_out<<<BT / 128, 256>>>(g3, b3, bc, out);
}

// round 15
// speedup vs baseline: 1.0913x; 1.0913x over previous
#include <cuda_runtime.h>
#include <cuda_fp16.h>
#include <math.h>
#include <stdint.h>

// Problem constants
#define BB   2048
#define TT   32
#define BT   65536        // BB*TT
#define DIN_ 1024
#define DH_  64
#define HH   512
#define G4   2048         // 4*H
#define KIN  576          // DH + H
#define AA   64

typedef unsigned long long u64;

#define SW128(off) ((off) ^ (((off) >> 3) & 0x70))

// ======================= helpers =======================
__device__ __forceinline__ uint32_t smem_to_u32(const void* p) {
    uint32_t a;
    asm("{ .reg .u64 t; cvta.to.shared.u64 t, %1; cvt.u32.u64 %0, t; }" : "=r"(a) : "l"(p));
    return a;
}
__device__ __forceinline__ void cpa16(uint32_t s, const void* g) {
    asm volatile("cp.async.cg.shared.global [%0], [%1], 16;" :: "r"(s), "l"(g));
}
#define CP_COMMIT() asm volatile("cp.async.commit_group;" ::: "memory")
#define CP_WAIT(n)  asm volatile("cp.async.wait_group %0;" :: "n"(n) : "memory")
__device__ __forceinline__ void ldsm4(uint32_t* r, uint32_t addr) {
    asm volatile("ldmatrix.sync.aligned.m8n8.x4.shared.b16 {%0,%1,%2,%3}, [%4];"
        : "=r"(r[0]), "=r"(r[1]), "=r"(r[2]), "=r"(r[3]) : "r"(addr));
}
__device__ __forceinline__ void mma16816h(float* c, const uint32_t* a, const uint32_t* b) {
    asm volatile("mma.sync.aligned.m16n8k16.row.col.f32.f16.f16.f32 "
        "{%0,%1,%2,%3}, {%4,%5,%6,%7}, {%8,%9}, {%0,%1,%2,%3};"
        : "+f"(c[0]), "+f"(c[1]), "+f"(c[2]), "+f"(c[3])
        : "r"(a[0]), "r"(a[1]), "r"(a[2]), "r"(a[3]), "r"(b[0]), "r"(b[1]));
}
__device__ __forceinline__ u64 pkh4(float a, float b, float c, float d) {
    __half2 lo = __floats2half2_rn(a, b);
    __half2 hi = __floats2half2_rn(c, d);
    u64 r;
    asm("mov.b64 %0, {%1, %2};" : "=l"(r) : "r"(*(uint32_t*)&lo), "r"(*(uint32_t*)&hi));
    return r;
}
// fast gates
__device__ __forceinline__ float tapx(float x) {
    float y; asm("tanh.approx.f32 %0, %1;" : "=f"(y) : "f"(x)); return y;
}
__device__ __forceinline__ float sigax(float x) { return fmaf(tapx(0.5f * x), 0.5f, 0.5f); }
// accurate-ish tanh for final output
__device__ __forceinline__ float ftanh(float x) { return 1.f - __fdividef(2.f, __expf(2.f * x) + 1.f); }

// ======================= scratch (device globals) =======================
__device__ __half g_xph[BT * DH_];               // x (fp16)  [(b*T+t)*64+d]
__device__ __half g_wph[2][8][256 * 576];        // LSTM W [dir][nb][n'(256)*576+k], n'=nl*4+gate
__device__ __half g_wdh[64 * 1024];              // Wd^T  [n(64)][k(1024)]
__device__ __half g_wch[64 * 1024];              // Wc^T  [a(64)][h(1024)]
__device__ __half g_hh[2][2][BB * HH];           // [dir][buf][b*512+n]
__device__ __half g_hcatH[BT * 2 * HH];          // [b][t][1024] masked, bw at reversed t
__device__ float g_mu3[BB];
__device__ float g_rs3[BB];
__device__ unsigned g_bar[32];                   // group barriers, zero-init

__device__ __forceinline__ void bar_arrive_release(unsigned* addr) {
    asm volatile("red.release.gpu.global.add.u32 [%0], 1;" :: "l"(addr) : "memory");
}
__device__ __forceinline__ unsigned bar_ld_acquire(unsigned* addr) {
    unsigned v;
    asm volatile("ld.acquire.gpu.global.u32 %0, [%1];" : "=r"(v) : "l"(addr) : "memory");
    return v;
}

// ---------------- KP: prepack LSTM W into fp16, gate-interleaved, K-major ----------------
__global__ void kp_w(const float* __restrict__ Wfw, const float* __restrict__ Wbw) {
    int idx = blockIdx.x * 256 + threadIdx.x;    // 2 * 576 * 2048 total
    int dir = idx >= (KIN * G4);
    int r = idx - dir * (KIN * G4);
    int k = r >> 11;
    int col = r & 2047;
    const float* W = dir ? Wbw : Wfw;
    float v = W[(size_t)k * G4 + col];
    int g = col >> 9, rr = col & 511, nb = rr >> 6, nl = rr & 63;
    int np = nl * 4 + g;
    g_wph[dir][nb][np * 576 + k] = __float2half(v);
}

// ---------------- KP2: transpose-pack Wd and Wc to fp16 [n][k] ----------------
__global__ void kp_dc(const float* __restrict__ Wd, const float* __restrict__ Wc) {
    int idx = blockIdx.x * 256 + threadIdx.x;    // 2 * 65536
    int which = idx >= 65536;
    int r = idx & 65535;
    int k = r >> 6, n = r & 63;
    if (!which) g_wdh[n * 1024 + k] = __float2half(Wd[(size_t)k * 64 + n]);
    else        g_wch[n * 1024 + k] = __float2half(Wc[(size_t)k * 64 + n]);
}

// ---------------- K1: LN1-stats (fused) -> LN1 -> dense(HMMA) -> LN2 -> relu -> fp16 ----------------
// grid 512, 256 threads (8 warps: 4m x 2n), CTA tile 128x64, K=1024 in 16 chunks of 64.
// Row stats kept in smem (not regs); occupancy forced to 2 CTAs/SM for latency hiding.
__global__ void __launch_bounds__(256, 2)
k1_dense(const float* __restrict__ ud,
         const float* __restrict__ g1, const float* __restrict__ b1,
         const float* __restrict__ bd,
         const float* __restrict__ g2, const float* __restrict__ b2) {
    __shared__ __align__(16) char sm1[33792];    // A 16K | B 2x8K ; buf f32[128][65] aliases
    __shared__ float g1s[1024], b1s[1024];
    __shared__ float smuA[128], srsA[128];       // LN1 row stats
    __shared__ float smu[128], srs[128];         // LN2 row stats
    uint32_t s32 = smem_to_u32(sm1);
    float* buf = (float*)sm1;

    int tid = threadIdx.x;
    int wid = tid >> 5, lid = tid & 31;
    int bx = blockIdx.x;
    int wm = wid & 3, wn = wid >> 2;
    int l2 = lid & 3;

    #pragma unroll
    for (int i = 0; i < 4; i++) { g1s[tid + i * 256] = g1[tid + i * 256]; b1s[tid + i * 256] = b1[tid + i * 256]; }

    // ---- pass 1: LN1 stats, 16 lanes per row, 8 rows per thread -> smem ----
    int rowL = tid >> 4, cl = tid & 15;
    #pragma unroll 1
    for (int it = 0; it < 8; it++) {
        int r = rowL + it * 16;
        const float4* p = (const float4*)(ud + (size_t)(bx * 128 + r) * DIN_) + cl;
        float s = 0.f, q = 0.f;
        #pragma unroll
        for (int c = 0; c < 16; c++) {
            float4 v = p[c * 16];
            s += v.x + v.y + v.z + v.w;
            q += v.x * v.x + v.y * v.y + v.z * v.z + v.w * v.w;
        }
        #pragma unroll
        for (int o = 1; o < 16; o <<= 1) {
            s += __shfl_xor_sync(0xffffffffu, s, o);
            q += __shfl_xor_sync(0xffffffffu, q, o);
        }
        if (cl == 0) {
            float mu = s / 1024.f;
            smuA[r] = mu;
            srsA[r] = rsqrtf(q / 1024.f - mu * mu + 1e-12f);
        }
    }
    __syncthreads();

    uint32_t aSts[8];
    #pragma unroll
    for (int it = 0; it < 8; it++)
        aSts[it] = SW128((uint32_t)((rowL + it * 16) * 128 + cl * 8));

    uint32_t swB[2]; int bofs[2];
    #pragma unroll
    for (int i = 0; i < 2; i++) {
        int idx = tid + i * 256;
        int row = idx >> 3, q = idx & 7;
        swB[i] = SW128((uint32_t)(row * 128 + q * 16));
        bofs[i] = row * 1024 + q * 8;
    }

    int lar = (lid & 7) + ((lid >> 3) & 1) * 8;
    int lac2 = ((lid >> 4) & 1) * 16;
    int lbr = (lid & 7) + ((lid >> 4) & 1) * 8;
    int lbc2 = ((lid >> 3) & 1) * 16;
    uint32_t aBase[2], aXor[2], bBase[2], bXor[2];
    #pragma unroll
    for (int mt = 0; mt < 2; mt++) {
        int r = wm * 32 + mt * 16 + lar;
        aBase[mt] = (uint32_t)(r * 128);
        aXor[mt] = (uint32_t)((r & 7) << 4);
    }
    #pragma unroll
    for (int np = 0; np < 2; np++) {
        int r = wn * 32 + np * 16 + lbr;
        bBase[np] = (uint32_t)(r * 128);
        bXor[np] = (uint32_t)((r & 7) << 4);
    }

    float acc[2][4][4];
    #pragma unroll
    for (int mt = 0; mt < 2; mt++)
        #pragma unroll
        for (int nt = 0; nt < 4; nt++)
            #pragma unroll
            for (int j = 0; j < 4; j++) acc[mt][nt][j] = 0.f;

    u64 regA[8];
    auto doLoadA = [&](int kc) {
        float4 gg = *(const float4*)&g1s[kc * 64 + cl * 4];
        float4 bbv = *(const float4*)&b1s[kc * 64 + cl * 4];
        #pragma unroll
        for (int it = 0; it < 8; it++) {
            int r = rowL + it * 16;
            float4 v = *(const float4*)(ud + (size_t)(bx * 128 + r) * DIN_ + kc * 64 + cl * 4);
            float mu = smuA[r], rs = srsA[r];
            regA[it] = pkh4((v.x - mu) * rs * gg.x + bbv.x,
                            (v.y - mu) * rs * gg.y + bbv.y,
                            (v.z - mu) * rs * gg.z + bbv.z,
                            (v.w - mu) * rs * gg.w + bbv.w);
        }
    };
    auto doStsA = [&]() {
        #pragma unroll
        for (int it = 0; it < 8; it++)
            *(u64*)(sm1 + aSts[it]) = regA[it];
    };
    auto doCpaB = [&](int kc, int st) {
        uint32_t sb = s32 + 16384 + (uint32_t)st * 8192u;
        #pragma unroll
        for (int i = 0; i < 2; i++)
            cpa16(sb + swB[i], g_wdh + bofs[i] + kc * 64);
        CP_COMMIT();
    };

    doLoadA(0);
    doCpaB(0, 0);
    int st = 0;

    #pragma unroll 1
    for (int kc = 0; kc < 16; kc++) {
        __syncthreads();
        if (kc < 15) doCpaB(kc + 1, st ^ 1);
        if (kc < 15) { CP_WAIT(1); } else { CP_WAIT(0); }
        doStsA();
        if (kc < 15) doLoadA(kc + 1);
        __syncthreads();

        uint32_t bS = s32 + 16384 + (uint32_t)st * 8192u;
        #pragma unroll
        for (int kt = 0; kt < 4; kt++) {
            uint32_t ah[2][4], bf[2][4];
            #pragma unroll
            for (int mt = 0; mt < 2; mt++) {
                uint32_t cb = ((uint32_t)(kt * 32 + lac2)) ^ aXor[mt];
                ldsm4(ah[mt], s32 + aBase[mt] + cb);
            }
            #pragma unroll
            for (int np = 0; np < 2; np++) {
                uint32_t cb = ((uint32_t)(kt * 32 + lbc2)) ^ bXor[np];
                ldsm4(bf[np], bS + bBase[np] + cb);
            }
            #pragma unroll
            for (int mt = 0; mt < 2; mt++)
                #pragma unroll
                for (int nt = 0; nt < 4; nt++)
                    mma16816h(acc[mt][nt], ah[mt], &bf[nt >> 1][(nt & 1) * 2]);
        }
        st ^= 1;
    }

    __syncthreads();   // all MMA done; smem now reused as buf

    #pragma unroll
    for (int mt = 0; mt < 2; mt++) {
        int r = wm * 32 + mt * 16 + (lid >> 2);
        #pragma unroll
        for (int nt = 0; nt < 4; nt++) {
            int c = wn * 32 + nt * 8 + l2 * 2;
            float b0 = bd[c], b1v = bd[c + 1];
            buf[r * 65 + c]           = acc[mt][nt][0] + b0;
            buf[r * 65 + c + 1]       = acc[mt][nt][1] + b1v;
            buf[(r + 8) * 65 + c]     = acc[mt][nt][2] + b0;
            buf[(r + 8) * 65 + c + 1] = acc[mt][nt][3] + b1v;
        }
    }
    __syncthreads();

    if (tid < 128) {
        float s = 0.f, q = 0.f;
        #pragma unroll
        for (int c = 0; c < 64; c++) { float v = buf[tid * 65 + c]; s += v; q += v * v; }
        float mu = s / 64.f;
        smu[tid] = mu;
        srs[tid] = rsqrtf(q / 64.f - mu * mu + 1e-12f);
    }
    __syncthreads();

    int ty = tid >> 4, tx = tid & 15;
    #pragma unroll
    for (int r = 0; r < 8; r++) {
        int lr = ty * 8 + r;
        float mu = smu[lr], rs = srs[lr];
        int gr = bx * 128 + lr;
        #pragma unroll
        for (int j = 0; j < 4; j++) {
            int c = tx * 4 + j;
            float y = (buf[lr * 65 + c] - mu) * rs * g2[c] + b2[c];
            g_xph[(size_t)gr * DH_ + c] = __float2half(fmaxf(y, 0.f));
        }
    }
}

// ---------------- K2P: persistent bidirectional LSTM (8 warps, 64x64 warp tiles) ----------------
__global__ void __launch_bounds__(256, 1)
k2p_persist(const float* __restrict__ bfw, const float* __restrict__ bbw,
            const int* __restrict__ au) {
    extern __shared__ __align__(16) char dsm[];

    int tid = threadIdx.x;
    int wid = tid >> 5, lid = tid & 31;
    int bx = blockIdx.x, npair = blockIdx.y, dir = blockIdx.z;
    int wm = wid >> 2, wn = wid & 3;          // warp grid 2m x 4n
    int grp = dir * 16 + bx;

    uint32_t b32 = smem_to_u32(dsm);
    uint32_t tb32 = (b32 + 1023) & ~1023u;
    char* tb = dsm + (tb32 - b32);
    float* cS = (float*)(tb + 147456);            // c-state [128][129] f32
    char*  hst = tb + 147456 + 66048;             // h-stage [128][68] fp16

    const float* bias = dir ? bbw : bfw;

    uint32_t swA[4]; int gbA[4], qA8[4], aA[4];
    #pragma unroll
    for (int i = 0; i < 4; i++) {
        int idx = tid + i * 256;
        int row = idx >> 3, q = idx & 7;
        swA[i] = SW128((uint32_t)(row * 128 + q * 16));
        gbA[i] = bx * 128 + row;
        qA8[i] = q * 8;
        aA[i] = au[gbA[i]];
    }
    uint32_t swB[8]; int boff[8];
    #pragma unroll
    for (int i = 0; i < 8; i++) {
        int idx = tid + i * 256;
        int row = idx >> 3, q = idx & 7;
        swB[i] = SW128((uint32_t)(row * 128 + q * 16));
        boff[i] = row * KIN + q * 8;
    }

    int lar = (lid & 7) + ((lid >> 3) & 1) * 8;
    int lac2 = ((lid >> 4) & 1) * 16;
    int lbr = (lid & 7) + ((lid >> 4) & 1) * 8;
    int lbc2 = ((lid >> 3) & 1) * 16;
    uint32_t aBase[4], aXor[4], bBase[4], bXor[4];
    #pragma unroll
    for (int mt = 0; mt < 4; mt++) {
        int r = wm * 64 + mt * 16 + lar;
        aBase[mt] = (uint32_t)(r * 128);
        aXor[mt] = (uint32_t)((r & 7) << 4);
    }
    #pragma unroll
    for (int np = 0; np < 4; np++) {
        int r = wn * 64 + np * 16 + lbr;
        bBase[np] = (uint32_t)(r * 128);
        bXor[np] = (uint32_t)((r & 7) << 4);
    }

    int l2 = lid & 3;
    int erow[4];
    #pragma unroll
    for (int mt = 0; mt < 4; mt++)
        erow[mt] = wm * 64 + mt * 16 + (lid >> 2) + (l2 & 1) * 8;

    int auC[8];
    #pragma unroll
    for (int i = 0; i < 8; i++) auC[i] = au[bx * 128 + (tid >> 4) + i * 16];

    float acc[4][8][4];
    #pragma unroll
    for (int mt = 0; mt < 4; mt++)
        #pragma unroll
        for (int nt = 0; nt < 8; nt++)
            #pragma unroll
            for (int j = 0; j < 4; j++) acc[mt][nt][j] = 0.f;

    int sbuf = 0, cbuf = 0;

    auto issueC = [&](int t, int ci) {
        int NC = (t == 0) ? 1 : 9;
        int half = (ci >= NC) ? 1 : 0;
        int kc = ci - half * NC;
        uint32_t sb = tb32 + (uint32_t)sbuf * 49152u;
        if (kc == 0) {
            #pragma unroll
            for (int i = 0; i < 4; i++) {
                int ts = t;
                if (dir) ts = (t < aA[i]) ? (aA[i] - 1 - t) : t;
                cpa16(sb + swA[i], g_xph + (gbA[i] * TT + ts) * DH_ + qA8[i]);
            }
        } else {
            const __half* hp = g_hh[dir][(t & 1) ^ 1];
            int e0 = (kc - 1) * 64;
            #pragma unroll
            for (int i = 0; i < 4; i++)
                cpa16(sb + swA[i], hp + gbA[i] * HH + e0 + qA8[i]);
        }
        int nb = npair * 2 + half;
        const __half* wp = g_wph[dir][nb];
        int ke = kc * 64;
        #pragma unroll
        for (int i = 0; i < 8; i++)
            cpa16(sb + 16384 + swB[i], wp + boff[i] + ke);
        CP_COMMIT();
        sbuf = (sbuf == 2) ? 0 : sbuf + 1;
    };

    int pending = 0;

    #pragma unroll 1
    for (int t = 0; t < TT; t++) {
        int NC = (t == 0) ? 1 : 9;
        int NC2 = 2 * NC;

        int issued = pending;
        while (issued < NC2 && issued < 2) { issueC(t, issued); issued++; }

        #pragma unroll 1
        for (int ci = 0; ci < NC2; ci++) {
            if (issued - ci >= 2) CP_WAIT(1);
            else                  CP_WAIT(0);
            __syncthreads();
            if (issued < NC2) { issueC(t, issued); issued++; }

            uint32_t sb = tb32 + (uint32_t)cbuf * 49152u;
            cbuf = (cbuf == 2) ? 0 : cbuf + 1;

            #pragma unroll
            for (int kt = 0; kt < 4; kt++) {
                uint32_t ah[4][4], bf[4][4];
                #pragma unroll
                for (int mt = 0; mt < 4; mt++) {
                    uint32_t cb = ((uint32_t)(kt * 32 + lac2)) ^ aXor[mt];
                    ldsm4(ah[mt], sb + aBase[mt] + cb);
                }
                #pragma unroll
                for (int np = 0; np < 4; np++) {
                    uint32_t cb = ((uint32_t)(kt * 32 + lbc2)) ^ bXor[np];
                    ldsm4(bf[np], sb + 16384 + bBase[np] + cb);
                }
                #pragma unroll
                for (int mt = 0; mt < 4; mt++)
                    #pragma unroll
                    for (int nt = 0; nt < 8; nt++)
                        mma16816h(acc[mt][nt], ah[mt], &bf[nt >> 1][(nt & 1) * 2]);
            }

            if (ci == NC - 1 || ci == NC2 - 1) {
                int half = (ci >= NC) ? 1 : 0;
                int nb = npair * 2 + half;
                bool oddl = (l2 & 1);
                #pragma unroll
                for (int mt = 0; mt < 4; mt++) {
                    int row = erow[mt];
                    #pragma unroll
                    for (int nt = 0; nt < 8; nt++) {
                        float o0 = acc[mt][nt][0], o1 = acc[mt][nt][1];
                        float o2 = acc[mt][nt][2], o3 = acc[mt][nt][3];
                        float r0 = __shfl_xor_sync(0xffffffffu, o0, 1);
                        float r1 = __shfl_xor_sync(0xffffffffu, o1, 1);
                        float r2 = __shfl_xor_sync(0xffffffffu, o2, 1);
                        float r3 = __shfl_xor_sync(0xffffffffu, o3, 1);
                        float zi, zj, zf, zo;
                        if (!oddl) { zi = o0; zj = o1; zf = r0; zo = r1; }
                        else       { zi = r2; zj = r3; zf = o2; zo = o3; }
                        int u = wn * 16 + nt * 2 + (l2 >> 1);
                        int n = nb * 64 + u;
                        float vi = zi + bias[n];
                        float vj = zj + bias[HH + n];
                        float vf = zf + bias[2 * HH + n];
                        float vo = zo + bias[3 * HH + n];
                        int cidx = row * 129 + half * 64 + u;
                        float cp = (t == 0) ? 0.f : cS[cidx];
                        float cn = cp * sigax(vf + 1.0f) + sigax(vi) * tapx(vj);
                        float hn = tapx(cn) * sigax(vo);
                        cS[cidx] = cn;
                        *(__half*)(hst + (row * 68 + u) * 2) = __float2half(hn);
                    }
                }
                #pragma unroll
                for (int mt = 0; mt < 4; mt++)
                    #pragma unroll
                    for (int nt = 0; nt < 8; nt++)
                        #pragma unroll
                        for (int j = 0; j < 4; j++) acc[mt][nt][j] = 0.f;

                __syncthreads();
                // coalesced copy h-stage -> g_hh (unmasked, for recurrence)
                __half* oh = g_hh[dir][t & 1];
                #pragma unroll
                for (int i = 0; i < 8; i++) {
                    int idx = tid + i * 256;
                    int row = idx >> 4, ch = idx & 15;
                    u64 v = *(const u64*)(hst + row * 136 + ch * 8);
                    *(u64*)((char*)oh + ((size_t)(bx * 128 + row) * HH + nb * 64 + ch * 4) * 2) = v;
                }
                // masked (+ reversed for bw) copy -> g_hcatH fp16 [b][t][1024]
                #pragma unroll
                for (int i = 0; i < 8; i++) {
                    int idx = tid + i * 256;
                    int row = idx >> 4, ch = idx & 15;
                    int gb = bx * 128 + row;
                    int a0 = auC[i];
                    u64 v = *(const u64*)(hst + row * 136 + ch * 8);
                    int ts;
                    if (t < a0) ts = dir ? (a0 - 1 - t) : t;
                    else { ts = t; v = 0ull; }
                    *(u64*)((char*)g_hcatH +
                        (((size_t)gb * TT + ts) * (2 * HH) + dir * HH + nb * 64 + ch * 4) * 2) = v;
                }
            }
        }

        if (t < TT - 1) {
            issueC(t + 1, 0);
            pending = 1;
            __syncthreads();   // all threads' g_hh stores happen-before tid0's release (bar.sync h-b)
            if (tid == 0) {
                bar_arrive_release(&g_bar[grp]);
                unsigned target = 4u * (unsigned)(t + 1);
                while (bar_ld_acquire(&g_bar[grp]) < target) __nanosleep(64);
            }
            __syncthreads();   // acquire result propagated to whole CTA
        }
    }

    // final arrival + reset for graph-replay determinism
    __syncthreads();
    if (tid == 0) {
        bar_arrive_release(&g_bar[grp]);
        if (npair == 0) {
            while (bar_ld_acquire(&g_bar[grp]) < 4u * (unsigned)TT) __nanosleep(64);
            g_bar[grp] = 0u;
            __threadfence();
        }
    }
}

// ---------------- K3: per-batch LN3 stats over contiguous fp16 [b][32768] ----------------
__global__ void k3_stats() {
    __shared__ float ssum[256], ssq[256];
    int b = blockIdx.x, tid = threadIdx.x;
    const uint4* p = (const uint4*)(g_hcatH + (size_t)b * (TT * 2 * HH));
    float s = 0.f, q = 0.f;
    #pragma unroll 4
    for (int i = 0; i < 16; i++) {
        uint4 v = p[tid + i * 256];
        const __half* hv = (const __half*)&v;
        #pragma unroll
        for (int e = 0; e < 8; e++) {
            float f = __half2float(hv[e]);
            s += f; q += f * f;
        }
    }
    ssum[tid] = s; ssq[tid] = q;
    __syncthreads();
    for (int o = 128; o; o >>= 1) {
        if (tid < o) { ssum[tid] += ssum[tid + o]; ssq[tid] += ssq[tid + o]; }
        __syncthreads();
    }
    if (tid == 0) {
        float mu = ssum[0] / 32768.f;
        g_mu3[b] = mu;
        g_rs3[b] = rsqrtf(ssq[0] / 32768.f - mu * mu + 1e-12f);
    }
}

// ---------------- K4: relu(LN3) -> conv(HMMA) -> +bc -> tanh -> out ----------------
__global__ void __launch_bounds__(256, 2)
k4_out(const float* __restrict__ g3, const float* __restrict__ b3,
       const float* __restrict__ bc, float* __restrict__ out) {
    __shared__ __align__(16) char sm4[32768];    // A 16K | B 2x8K
    __shared__ float g3s[1024], b3s[1024];
    uint32_t s32 = smem_to_u32(sm4);

    int tid = threadIdx.x;
    int wid = tid >> 5, lid = tid & 31;
    int bx = blockIdx.x;
    int wm = wid & 3, wn = wid >> 2;
    int l2 = lid & 3;

    #pragma unroll
    for (int i = 0; i < 4; i++) { g3s[tid + i * 256] = g3[tid + i * 256]; b3s[tid + i * 256] = b3[tid + i * 256]; }

    int rowL = tid >> 3, cl = tid & 7;
    float amus[4], arss[4];
    uint32_t aSts[4];
    #pragma unroll
    for (int it = 0; it < 4; it++) {
        int r = rowL + it * 32;
        int bat = (bx * 128 + r) >> 5;
        amus[it] = g_mu3[bat];
        arss[it] = g_rs3[bat];
        aSts[it] = SW128((uint32_t)(r * 128 + cl * 16));
    }
    __syncthreads();

    uint32_t swB[2]; int bofs[2];
    #pragma unroll
    for (int i = 0; i < 2; i++) {
        int idx = tid + i * 256;
        int row = idx >> 3, q = idx & 7;
        swB[i] = SW128((uint32_t)(row * 128 + q * 16));
        bofs[i] = row * 1024 + q * 8;
    }

    int lar = (lid & 7) + ((lid >> 3) & 1) * 8;
    int lac2 = ((lid >> 4) & 1) * 16;
    int lbr = (lid & 7) + ((lid >> 4) & 1) * 8;
    int lbc2 = ((lid >> 3) & 1) * 16;
    uint32_t aBase[2], aXor[2], bBase[2], bXor[2];
    #pragma unroll
    for (int mt = 0; mt < 2; mt++) {
        int r = wm * 32 + mt * 16 + lar;
        aBase[mt] = (uint32_t)(r * 128);
        aXor[mt] = (uint32_t)((r & 7) << 4);
    }
    #pragma unroll
    for (int np = 0; np < 2; np++) {
        int r = wn * 32 + np * 16 + lbr;
        bBase[np] = (uint32_t)(r * 128);
        bXor[np] = (uint32_t)((r & 7) << 4);
    }

    float acc[2][4][4];
    #pragma unroll
    for (int mt = 0; mt < 2; mt++)
        #pragma unroll
        for (int nt = 0; nt < 4; nt++)
            #pragma unroll
            for (int j = 0; j < 4; j++) acc[mt][nt][j] = 0.f;

    uint4 regA[4];
    auto doLoadA = [&](int kc) {
        float4 gg0 = *(const float4*)&g3s[kc * 64 + cl * 8];
        float4 gg1 = *(const float4*)&g3s[kc * 64 + cl * 8 + 4];
        float4 bb0 = *(const float4*)&b3s[kc * 64 + cl * 8];
        float4 bb1 = *(const float4*)&b3s[kc * 64 + cl * 8 + 4];
        #pragma unroll
        for (int it = 0; it < 4; it++) {
            int r = rowL + it * 32;
            uint4 v = *(const uint4*)(g_hcatH + (size_t)(bx * 128 + r) * (2 * HH) + kc * 64 + cl * 8);
            const __half* hv = (const __half*)&v;
            float amu = amus[it], ars = arss[it];
            uint4 o;
            __half* ho = (__half*)&o;
            ho[0] = __float2half(fmaxf((__half2float(hv[0]) - amu) * ars * gg0.x + bb0.x, 0.f));
            ho[1] = __float2half(fmaxf((__half2float(hv[1]) - amu) * ars * gg0.y + bb0.y, 0.f));
            ho[2] = __float2half(fmaxf((__half2float(hv[2]) - amu) * ars * gg0.z + bb0.z, 0.f));
            ho[3] = __float2half(fmaxf((__half2float(hv[3]) - amu) * ars * gg0.w + bb0.w, 0.f));
            ho[4] = __float2half(fmaxf((__half2float(hv[4]) - amu) * ars * gg1.x + bb1.x, 0.f));
            ho[5] = __float2half(fmaxf((__half2float(hv[5]) - amu) * ars * gg1.y + bb1.y, 0.f));
            ho[6] = __float2half(fmaxf((__half2float(hv[6]) - amu) * ars * gg1.z + bb1.z, 0.f));
            ho[7] = __float2half(fmaxf((__half2float(hv[7]) - amu) * ars * gg1.w + bb1.w, 0.f));
            regA[it] = o;
        }
    };
    auto doStsA = [&]() {
        #pragma unroll
        for (int it = 0; it < 4; it++)
            *(uint4*)(sm4 + aSts[it]) = regA[it];
    };
    auto doCpaB = [&](int kc, int st) {
        uint32_t sb = s32 + 16384 + (uint32_t)st * 8192u;
        #pragma unroll
        for (int i = 0; i < 2; i++)
            cpa16(sb + swB[i], g_wch + bofs[i] + kc * 64);
        CP_COMMIT();
    };

    doLoadA(0);
    doCpaB(0, 0);
    int st = 0;

    #pragma unroll 1
    for (int kc = 0; kc < 16; kc++) {
        __syncthreads();
        if (kc < 15) doCpaB(kc + 1, st ^ 1);
        if (kc < 15) { CP_WAIT(1); } else { CP_WAIT(0); }
        doStsA();
        if (kc < 15) doLoadA(kc + 1);
        __syncthreads();

        uint32_t bS = s32 + 16384 + (uint32_t)st * 8192u;
        #pragma unroll
        for (int kt = 0; kt < 4; kt++) {
            uint32_t ah[2][4], bf[2][4];
            #pragma unroll
            for (int mt = 0; mt < 2; mt++) {
                uint32_t cb = ((uint32_t)(kt * 32 + lac2)) ^ aXor[mt];
                ldsm4(ah[mt], s32 + aBase[mt] + cb);
            }
            #pragma unroll
            for (int np = 0; np < 2; np++) {
                uint32_t cb = ((uint32_t)(kt * 32 + lbc2)) ^ bXor[np];
                ldsm4(bf[np], bS + bBase[np] + cb);
            }
            #pragma unroll
            for (int mt = 0; mt < 2; mt++)
                #pragma unroll
                for (int nt = 0; nt < 4; nt++)
                    mma16816h(acc[mt][nt], ah[mt], &bf[nt >> 1][(nt & 1) * 2]);
        }
        st ^= 1;
    }

    #pragma unroll
    for (int mt = 0; mt < 2; mt++) {
        int r = wm * 32 + mt * 16 + (lid >> 2);
        int gr = bx * 128 + r;
        #pragma unroll
        for (int nt = 0; nt < 4; nt++) {
            int c = wn * 32 + nt * 8 + l2 * 2;
            float b0 = bc[c], b1v = bc[c + 1];
            float2 v0 = make_float2(ftanh(acc[mt][nt][0] + b0), ftanh(acc[mt][nt][1] + b1v));
            float2 v1 = make_float2(ftanh(acc[mt][nt][2] + b0), ftanh(acc[mt][nt][3] + b1v));
            *(float2*)(out + (size_t)gr * AA + c) = v0;
            *(float2*)(out + (size_t)(gr + 8) * AA + c) = v1;
        }
    }
}

// ---------------- launch ----------------
extern "C" void kernel_launch(void* const* d_in, const int* in_sizes, int n_in,
                              void* d_out, int out_size) {
    int s = (n_in >= 18) ? 1 : 0;
    const float* ud  = (const float*)d_in[0];
    const int*   au  = (const int*)  d_in[2];
    const float* g1  = (const float*)d_in[3 + s];
    const float* b1  = (const float*)d_in[4 + s];
    const float* Wd  = (const float*)d_in[5 + s];
    const float* bd  = (const float*)d_in[6 + s];
    const float* g2  = (const float*)d_in[7 + s];
    const float* b2  = (const float*)d_in[8 + s];
    const float* Wfw = (const float*)d_in[9 + s];
    const float* bfw = (const float*)d_in[10 + s];
    const float* Wbw = (const float*)d_in[11 + s];
    const float* bbw = (const float*)d_in[12 + s];
    const float* g3  = (const float*)d_in[13 + s];
    const float* b3  = (const float*)d_in[14 + s];
    const float* Wc  = (const float*)d_in[15 + s];
    const float* bc  = (const float*)d_in[16 + s];
    float* out = (float*)d_out;

    const int K2_SMEM = 1024 + 3 * 49152 + 66048 + 17408;   // 231936 bytes
    cudaFuncSetAttribute(k2p_persist, cudaFuncAttributeMaxDynamicSharedMemorySize, K2_SMEM);

    kp_w<<<(2 * KIN * G4) / 256, 256>>>(Wfw, Wbw);
    kp_dc<<<512, 256>>>(Wd, Wc);
    k1_dense<<<BT / 128, 256>>>(ud, g1, b1, bd, g2, b2);
    k2p_persist<<<dim3(16, 4, 2), 256, K2_SMEM>>>(bfw, bbw, au);
    k3_stats<<<BB, 256>>>();
    k4_out<<<BT / 128, 256>>>(g3, b3, bc, out);
}

// round 16
// speedup vs baseline: 1.1035x; 1.0112x over previous
#include <cuda_runtime.h>
#include <cuda_fp16.h>
#include <math.h>
#include <stdint.h>

// Problem constants
#define BB   2048
#define TT   32
#define BT   65536        // BB*TT
#define DIN_ 1024
#define DH_  64
#define HH   512
#define G4   2048         // 4*H
#define KIN  576          // DH + H
#define AA   64

typedef unsigned long long u64;

#define SW128(off) ((off) ^ (((off) >> 3) & 0x70))

// ======================= helpers =======================
__device__ __forceinline__ uint32_t smem_to_u32(const void* p) {
    uint32_t a;
    asm("{ .reg .u64 t; cvta.to.shared.u64 t, %1; cvt.u32.u64 %0, t; }" : "=r"(a) : "l"(p));
    return a;
}
__device__ __forceinline__ void cpa16(uint32_t s, const void* g) {
    asm volatile("cp.async.cg.shared.global [%0], [%1], 16;" :: "r"(s), "l"(g));
}
#define CP_COMMIT() asm volatile("cp.async.commit_group;" ::: "memory")
#define CP_WAIT(n)  asm volatile("cp.async.wait_group %0;" :: "n"(n) : "memory")
__device__ __forceinline__ void ldsm4(uint32_t* r, uint32_t addr) {
    asm volatile("ldmatrix.sync.aligned.m8n8.x4.shared.b16 {%0,%1,%2,%3}, [%4];"
        : "=r"(r[0]), "=r"(r[1]), "=r"(r[2]), "=r"(r[3]) : "r"(addr));
}
__device__ __forceinline__ void mma16816h(float* c, const uint32_t* a, const uint32_t* b) {
    asm volatile("mma.sync.aligned.m16n8k16.row.col.f32.f16.f16.f32 "
        "{%0,%1,%2,%3}, {%4,%5,%6,%7}, {%8,%9}, {%0,%1,%2,%3};"
        : "+f"(c[0]), "+f"(c[1]), "+f"(c[2]), "+f"(c[3])
        : "r"(a[0]), "r"(a[1]), "r"(a[2]), "r"(a[3]), "r"(b[0]), "r"(b[1]));
}
__device__ __forceinline__ u64 pkh4(float a, float b, float c, float d) {
    __half2 lo = __floats2half2_rn(a, b);
    __half2 hi = __floats2half2_rn(c, d);
    u64 r;
    asm("mov.b64 %0, {%1, %2};" : "=l"(r) : "r"(*(uint32_t*)&lo), "r"(*(uint32_t*)&hi));
    return r;
}
// fast gates
__device__ __forceinline__ float tapx(float x) {
    float y; asm("tanh.approx.f32 %0, %1;" : "=f"(y) : "f"(x)); return y;
}
__device__ __forceinline__ float sigax(float x) { return fmaf(tapx(0.5f * x), 0.5f, 0.5f); }
// accurate-ish tanh for final output
__device__ __forceinline__ float ftanh(float x) { return 1.f - __fdividef(2.f, __expf(2.f * x) + 1.f); }

#define CLUSTER_ARRIVE() asm volatile("barrier.cluster.arrive.aligned;" ::: "memory")
#define CLUSTER_WAIT()   asm volatile("barrier.cluster.wait.aligned;" ::: "memory")

// ======================= scratch (device globals) =======================
__device__ __half g_xph[BT * DH_];               // x (fp16)  [(b*T+t)*64+d]
__device__ __half g_wph[2][8][256 * 576];        // LSTM W [dir][nb][n'(256)*576+k], n'=nl*4+gate
__device__ __half g_wdh[64 * 1024];              // Wd^T  [n(64)][k(1024)]
__device__ __half g_wch[64 * 1024];              // Wc^T  [a(64)][h(1024)]
__device__ __half g_hh[2][2][BB * HH];           // [dir][buf][b*512+n]
__device__ __half g_hcatH[BT * 2 * HH];          // [b][t][1024] masked, bw at reversed t
__device__ float g_s3[BB];                       // LN3 partial sums (zeroed by kp_w)
__device__ float g_q3[BB];
__device__ float g_mu3[BB];
__device__ float g_rs3[BB];

// ---------------- KP: prepack LSTM W into fp16, gate-interleaved, K-major (+ zero LN3 partials) ----------------
__global__ void kp_w(const float* __restrict__ Wfw, const float* __restrict__ Wbw) {
    int idx = blockIdx.x * 256 + threadIdx.x;    // 2 * 576 * 2048 total
    if (idx < BB) { g_s3[idx] = 0.f; g_q3[idx] = 0.f; }
    int dir = idx >= (KIN * G4);
    int r = idx - dir * (KIN * G4);
    int k = r >> 11;
    int col = r & 2047;
    const float* W = dir ? Wbw : Wfw;
    float v = W[(size_t)k * G4 + col];
    int g = col >> 9, rr = col & 511, nb = rr >> 6, nl = rr & 63;
    int np = nl * 4 + g;
    g_wph[dir][nb][np * 576 + k] = __float2half(v);
}

// ---------------- KP2: transpose-pack Wd and Wc to fp16 [n][k] ----------------
__global__ void kp_dc(const float* __restrict__ Wd, const float* __restrict__ Wc) {
    int idx = blockIdx.x * 256 + threadIdx.x;    // 2 * 65536
    int which = idx >= 65536;
    int r = idx & 65535;
    int k = r >> 6, n = r & 63;
    if (!which) g_wdh[n * 1024 + k] = __float2half(Wd[(size_t)k * 64 + n]);
    else        g_wch[n * 1024 + k] = __float2half(Wc[(size_t)k * 64 + n]);
}

// ---------------- K1: LN1-stats (fused) -> LN1 -> dense(HMMA) -> LN2 -> relu -> fp16 ----------------
__global__ void __launch_bounds__(256, 2)
k1_dense(const float* __restrict__ ud,
         const float* __restrict__ g1, const float* __restrict__ b1,
         const float* __restrict__ bd,
         const float* __restrict__ g2, const float* __restrict__ b2) {
    __shared__ __align__(16) char sm1[33792];    // A 16K | B 2x8K ; buf f32[128][65] aliases
    __shared__ float g1s[1024], b1s[1024];
    __shared__ float smuA[128], srsA[128];       // LN1 row stats
    __shared__ float smu[128], srs[128];         // LN2 row stats
    uint32_t s32 = smem_to_u32(sm1);
    float* buf = (float*)sm1;

    int tid = threadIdx.x;
    int wid = tid >> 5, lid = tid & 31;
    int bx = blockIdx.x;
    int wm = wid & 3, wn = wid >> 2;
    int l2 = lid & 3;

    #pragma unroll
    for (int i = 0; i < 4; i++) { g1s[tid + i * 256] = g1[tid + i * 256]; b1s[tid + i * 256] = b1[tid + i * 256]; }

    // ---- pass 1: LN1 stats, 16 lanes per row, 8 rows per thread -> smem ----
    int rowL = tid >> 4, cl = tid & 15;
    #pragma unroll 1
    for (int it = 0; it < 8; it++) {
        int r = rowL + it * 16;
        const float4* p = (const float4*)(ud + (size_t)(bx * 128 + r) * DIN_) + cl;
        float s = 0.f, q = 0.f;
        #pragma unroll
        for (int c = 0; c < 16; c++) {
            float4 v = p[c * 16];
            s += v.x + v.y + v.z + v.w;
            q += v.x * v.x + v.y * v.y + v.z * v.z + v.w * v.w;
        }
        #pragma unroll
        for (int o = 1; o < 16; o <<= 1) {
            s += __shfl_xor_sync(0xffffffffu, s, o);
            q += __shfl_xor_sync(0xffffffffu, q, o);
        }
        if (cl == 0) {
            float mu = s / 1024.f;
            smuA[r] = mu;
            srsA[r] = rsqrtf(q / 1024.f - mu * mu + 1e-12f);
        }
    }
    __syncthreads();

    uint32_t aSts[8];
    #pragma unroll
    for (int it = 0; it < 8; it++)
        aSts[it] = SW128((uint32_t)((rowL + it * 16) * 128 + cl * 8));

    uint32_t swB[2]; int bofs[2];
    #pragma unroll
    for (int i = 0; i < 2; i++) {
        int idx = tid + i * 256;
        int row = idx >> 3, q = idx & 7;
        swB[i] = SW128((uint32_t)(row * 128 + q * 16));
        bofs[i] = row * 1024 + q * 8;
    }

    int lar = (lid & 7) + ((lid >> 3) & 1) * 8;
    int lac2 = ((lid >> 4) & 1) * 16;
    int lbr = (lid & 7) + ((lid >> 4) & 1) * 8;
    int lbc2 = ((lid >> 3) & 1) * 16;
    uint32_t aBase[2], aXor[2], bBase[2], bXor[2];
    #pragma unroll
    for (int mt = 0; mt < 2; mt++) {
        int r = wm * 32 + mt * 16 + lar;
        aBase[mt] = (uint32_t)(r * 128);
        aXor[mt] = (uint32_t)((r & 7) << 4);
    }
    #pragma unroll
    for (int np = 0; np < 2; np++) {
        int r = wn * 32 + np * 16 + lbr;
        bBase[np] = (uint32_t)(r * 128);
        bXor[np] = (uint32_t)((r & 7) << 4);
    }

    float acc[2][4][4];
    #pragma unroll
    for (int mt = 0; mt < 2; mt++)
        #pragma unroll
        for (int nt = 0; nt < 4; nt++)
            #pragma unroll
            for (int j = 0; j < 4; j++) acc[mt][nt][j] = 0.f;

    u64 regA[8];
    auto doLoadA = [&](int kc) {
        float4 gg = *(const float4*)&g1s[kc * 64 + cl * 4];
        float4 bbv = *(const float4*)&b1s[kc * 64 + cl * 4];
        #pragma unroll
        for (int it = 0; it < 8; it++) {
            int r = rowL + it * 16;
            float4 v = *(const float4*)(ud + (size_t)(bx * 128 + r) * DIN_ + kc * 64 + cl * 4);
            float mu = smuA[r], rs = srsA[r];
            regA[it] = pkh4((v.x - mu) * rs * gg.x + bbv.x,
                            (v.y - mu) * rs * gg.y + bbv.y,
                            (v.z - mu) * rs * gg.z + bbv.z,
                            (v.w - mu) * rs * gg.w + bbv.w);
        }
    };
    auto doStsA = [&]() {
        #pragma unroll
        for (int it = 0; it < 8; it++)
            *(u64*)(sm1 + aSts[it]) = regA[it];
    };
    auto doCpaB = [&](int kc, int st) {
        uint32_t sb = s32 + 16384 + (uint32_t)st * 8192u;
        #pragma unroll
        for (int i = 0; i < 2; i++)
            cpa16(sb + swB[i], g_wdh + bofs[i] + kc * 64);
        CP_COMMIT();
    };

    doLoadA(0);
    doCpaB(0, 0);
    int st = 0;

    #pragma unroll 1
    for (int kc = 0; kc < 16; kc++) {
        __syncthreads();
        if (kc < 15) doCpaB(kc + 1, st ^ 1);
        if (kc < 15) { CP_WAIT(1); } else { CP_WAIT(0); }
        doStsA();
        if (kc < 15) doLoadA(kc + 1);
        __syncthreads();

        uint32_t bS = s32 + 16384 + (uint32_t)st * 8192u;
        #pragma unroll
        for (int kt = 0; kt < 4; kt++) {
            uint32_t ah[2][4], bf[2][4];
            #pragma unroll
            for (int mt = 0; mt < 2; mt++) {
                uint32_t cb = ((uint32_t)(kt * 32 + lac2)) ^ aXor[mt];
                ldsm4(ah[mt], s32 + aBase[mt] + cb);
            }
            #pragma unroll
            for (int np = 0; np < 2; np++) {
                uint32_t cb = ((uint32_t)(kt * 32 + lbc2)) ^ bXor[np];
                ldsm4(bf[np], bS + bBase[np] + cb);
            }
            #pragma unroll
            for (int mt = 0; mt < 2; mt++)
                #pragma unroll
                for (int nt = 0; nt < 4; nt++)
                    mma16816h(acc[mt][nt], ah[mt], &bf[nt >> 1][(nt & 1) * 2]);
        }
        st ^= 1;
    }

    __syncthreads();   // all MMA done; smem now reused as buf

    #pragma unroll
    for (int mt = 0; mt < 2; mt++) {
        int r = wm * 32 + mt * 16 + (lid >> 2);
        #pragma unroll
        for (int nt = 0; nt < 4; nt++) {
            int c = wn * 32 + nt * 8 + l2 * 2;
            float b0 = bd[c], b1v = bd[c + 1];
            buf[r * 65 + c]           = acc[mt][nt][0] + b0;
            buf[r * 65 + c + 1]       = acc[mt][nt][1] + b1v;
            buf[(r + 8) * 65 + c]     = acc[mt][nt][2] + b0;
            buf[(r + 8) * 65 + c + 1] = acc[mt][nt][3] + b1v;
        }
    }
    __syncthreads();

    if (tid < 128) {
        float s = 0.f, q = 0.f;
        #pragma unroll
        for (int c = 0; c < 64; c++) { float v = buf[tid * 65 + c]; s += v; q += v * v; }
        float mu = s / 64.f;
        smu[tid] = mu;
        srs[tid] = rsqrtf(q / 64.f - mu * mu + 1e-12f);
    }
    __syncthreads();

    int ty = tid >> 4, tx = tid & 15;
    #pragma unroll
    for (int r = 0; r < 8; r++) {
        int lr = ty * 8 + r;
        float mu = smu[lr], rs = srs[lr];
        int gr = bx * 128 + lr;
        #pragma unroll
        for (int j = 0; j < 4; j++) {
            int c = tx * 4 + j;
            float y = (buf[lr * 65 + c] - mu) * rs * g2[c] + b2[c];
            g_xph[(size_t)gr * DH_ + c] = __float2half(fmaxf(y, 0.f));
        }
    }
}

// ---------------- K2P: persistent bidirectional LSTM (cluster-per-group, fused LN3 partials) ----------------
// grid (16 Mblk, 4 nbPair, 2 dir) = 128 CTAs = 32 clusters of 4 (cluster spans npair).
__global__ void __launch_bounds__(256, 1) __cluster_dims__(1, 4, 1)
k2p_persist(const float* __restrict__ bfw, const float* __restrict__ bbw,
            const int* __restrict__ au) {
    extern __shared__ __align__(16) char dsm[];

    int tid = threadIdx.x;
    int wid = tid >> 5, lid = tid & 31;
    int bx = blockIdx.x, npair = blockIdx.y, dir = blockIdx.z;
    int wm = wid >> 2, wn = wid & 3;          // warp grid 2m x 4n

    uint32_t b32 = smem_to_u32(dsm);
    uint32_t tb32 = (b32 + 1023) & ~1023u;
    char* tb = dsm + (tb32 - b32);
    float* cS = (float*)(tb + 147456);            // c-state [128][129] f32
    char*  hst = tb + 147456 + 66048;             // h-stage [128][68] fp16

    const float* bias = dir ? bbw : bfw;

    uint32_t swA[4]; int gbA[4], qA8[4], aA[4];
    #pragma unroll
    for (int i = 0; i < 4; i++) {
        int idx = tid + i * 256;
        int row = idx >> 3, q = idx & 7;
        swA[i] = SW128((uint32_t)(row * 128 + q * 16));
        gbA[i] = bx * 128 + row;
        qA8[i] = q * 8;
        aA[i] = au[gbA[i]];
    }
    uint32_t swB[8]; int boff[8];
    #pragma unroll
    for (int i = 0; i < 8; i++) {
        int idx = tid + i * 256;
        int row = idx >> 3, q = idx & 7;
        swB[i] = SW128((uint32_t)(row * 128 + q * 16));
        boff[i] = row * KIN + q * 8;
    }

    int lar = (lid & 7) + ((lid >> 3) & 1) * 8;
    int lac2 = ((lid >> 4) & 1) * 16;
    int lbr = (lid & 7) + ((lid >> 4) & 1) * 8;
    int lbc2 = ((lid >> 3) & 1) * 16;
    uint32_t aBase[4], aXor[4], bBase[4], bXor[4];
    #pragma unroll
    for (int mt = 0; mt < 4; mt++) {
        int r = wm * 64 + mt * 16 + lar;
        aBase[mt] = (uint32_t)(r * 128);
        aXor[mt] = (uint32_t)((r & 7) << 4);
    }
    #pragma unroll
    for (int np = 0; np < 4; np++) {
        int r = wn * 64 + np * 16 + lbr;
        bBase[np] = (uint32_t)(r * 128);
        bXor[np] = (uint32_t)((r & 7) << 4);
    }

    int l2 = lid & 3;
    int erow[4], eau[4];
    float sA[4], qA[4];
    #pragma unroll
    for (int mt = 0; mt < 4; mt++) {
        erow[mt] = wm * 64 + mt * 16 + (lid >> 2) + (l2 & 1) * 8;
        eau[mt] = au[bx * 128 + erow[mt]];
        sA[mt] = 0.f; qA[mt] = 0.f;
    }

    float acc[4][8][4];
    #pragma unroll
    for (int mt = 0; mt < 4; mt++)
        #pragma unroll
        for (int nt = 0; nt < 8; nt++)
            #pragma unroll
            for (int j = 0; j < 4; j++) acc[mt][nt][j] = 0.f;

    int sbuf = 0, cbuf = 0;

    auto issueC = [&](int t, int ci) {
        int NC = (t == 0) ? 1 : 9;
        int half = (ci >= NC) ? 1 : 0;
        int kc = ci - half * NC;
        uint32_t sb = tb32 + (uint32_t)sbuf * 49152u;
        if (kc == 0) {
            #pragma unroll
            for (int i = 0; i < 4; i++) {
                int ts = t;
                if (dir) ts = (t < aA[i]) ? (aA[i] - 1 - t) : t;
                cpa16(sb + swA[i], g_xph + (gbA[i] * TT + ts) * DH_ + qA8[i]);
            }
        } else {
            const __half* hp = g_hh[dir][(t & 1) ^ 1];
            int e0 = (kc - 1) * 64;
            #pragma unroll
            for (int i = 0; i < 4; i++)
                cpa16(sb + swA[i], hp + gbA[i] * HH + e0 + qA8[i]);
        }
        int nb = npair * 2 + half;
        const __half* wp = g_wph[dir][nb];
        int ke = kc * 64;
        #pragma unroll
        for (int i = 0; i < 8; i++)
            cpa16(sb + 16384 + swB[i], wp + boff[i] + ke);
        CP_COMMIT();
        sbuf = (sbuf == 2) ? 0 : sbuf + 1;
    };

    int pending = 0;

    #pragma unroll 1
    for (int t = 0; t < TT; t++) {
        int NC = (t == 0) ? 1 : 9;
        int NC2 = 2 * NC;

        int issued = pending;
        while (issued < NC2 && issued < 2) { issueC(t, issued); issued++; }

        #pragma unroll 1
        for (int ci = 0; ci < NC2; ci++) {
            if (issued - ci >= 2) CP_WAIT(1);
            else                  CP_WAIT(0);
            __syncthreads();
            if (issued < NC2) { issueC(t, issued); issued++; }

            uint32_t sb = tb32 + (uint32_t)cbuf * 49152u;
            cbuf = (cbuf == 2) ? 0 : cbuf + 1;

            #pragma unroll
            for (int kt = 0; kt < 4; kt++) {
                uint32_t ah[4][4], bf[4][4];
                #pragma unroll
                for (int mt = 0; mt < 4; mt++) {
                    uint32_t cb = ((uint32_t)(kt * 32 + lac2)) ^ aXor[mt];
                    ldsm4(ah[mt], sb + aBase[mt] + cb);
                }
                #pragma unroll
                for (int np = 0; np < 4; np++) {
                    uint32_t cb = ((uint32_t)(kt * 32 + lbc2)) ^ bXor[np];
                    ldsm4(bf[np], sb + 16384 + bBase[np] + cb);
                }
                #pragma unroll
                for (int mt = 0; mt < 4; mt++)
                    #pragma unroll
                    for (int nt = 0; nt < 8; nt++)
                        mma16816h(acc[mt][nt], ah[mt], &bf[nt >> 1][(nt & 1) * 2]);
            }

            if (ci == NC - 1 || ci == NC2 - 1) {
                int half = (ci >= NC) ? 1 : 0;
                int nb = npair * 2 + half;
                bool oddl = (l2 & 1);
                #pragma unroll
                for (int mt = 0; mt < 4; mt++) {
                    int row = erow[mt];
                    bool m = (t < eau[mt]);
                    #pragma unroll
                    for (int nt = 0; nt < 8; nt++) {
                        float o0 = acc[mt][nt][0], o1 = acc[mt][nt][1];
                        float o2 = acc[mt][nt][2], o3 = acc[mt][nt][3];
                        float r0 = __shfl_xor_sync(0xffffffffu, o0, 1);
                        float r1 = __shfl_xor_sync(0xffffffffu, o1, 1);
                        float r2 = __shfl_xor_sync(0xffffffffu, o2, 1);
                        float r3 = __shfl_xor_sync(0xffffffffu, o3, 1);
                        float zi, zj, zf, zo;
                        if (!oddl) { zi = o0; zj = o1; zf = r0; zo = r1; }
                        else       { zi = r2; zj = r3; zf = o2; zo = o3; }
                        int u = wn * 16 + nt * 2 + (l2 >> 1);
                        int n = nb * 64 + u;
                        float vi = zi + bias[n];
                        float vj = zj + bias[HH + n];
                        float vf = zf + bias[2 * HH + n];
                        float vo = zo + bias[3 * HH + n];
                        int cidx = row * 129 + half * 64 + u;
                        float cp = (t == 0) ? 0.f : cS[cidx];
                        float cn = cp * sigax(vf + 1.0f) + sigax(vi) * tapx(vj);
                        float hn = tapx(cn) * sigax(vo);
                        cS[cidx] = cn;
                        *(__half*)(hst + (row * 68 + u) * 2) = __float2half(hn);
                        // fused LN3 partial sums (masked)
                        float hv = m ? hn : 0.f;
                        sA[mt] += hv;
                        qA[mt] = fmaf(hv, hv, qA[mt]);
                    }
                }
                #pragma unroll
                for (int mt = 0; mt < 4; mt++)
                    #pragma unroll
                    for (int nt = 0; nt < 8; nt++)
                        #pragma unroll
                        for (int j = 0; j < 4; j++) acc[mt][nt][j] = 0.f;

                __syncthreads();
                // coalesced copy h-stage -> g_hh (unmasked, for recurrence)
                __half* oh = g_hh[dir][t & 1];
                #pragma unroll
                for (int i = 0; i < 8; i++) {
                    int idx = tid + i * 256;
                    int row = idx >> 4, ch = idx & 15;
                    u64 v = *(const u64*)(hst + row * 136 + ch * 8);
                    *(u64*)((char*)oh + ((size_t)(bx * 128 + row) * HH + nb * 64 + ch * 4) * 2) = v;
                }
                // masked (+ reversed for bw) copy -> g_hcatH fp16 [b][t][1024]
                #pragma unroll
                for (int i = 0; i < 8; i++) {
                    int idx = tid + i * 256;
                    int row = idx >> 4, ch = idx & 15;
                    int gb = bx * 128 + row;
                    int a0 = au[gb];
                    u64 v = *(const u64*)(hst + row * 136 + ch * 8);
                    int ts;
                    if (t < a0) ts = dir ? (a0 - 1 - t) : t;
                    else { ts = t; v = 0ull; }
                    *(u64*)((char*)g_hcatH +
                        (((size_t)gb * TT + ts) * (2 * HH) + dir * HH + nb * 64 + ch * 4) * 2) = v;
                }
            }
        }

        if (t < TT - 1) {
            issueC(t + 1, 0);
            pending = 1;
            // cluster barrier: per-thread release/acquire covers g_hh stores
            CLUSTER_ARRIVE();
            CLUSTER_WAIT();
        }
    }

    // ---- end: reduce fused LN3 partials (rows) and add to global ----
    float* sRow = (float*)tb;            // stage smem free now
    float* qRow = (float*)(tb + 512);
    if (tid < 128) { sRow[tid] = 0.f; qRow[tid] = 0.f; }
    __syncthreads();
    #pragma unroll
    for (int mt = 0; mt < 4; mt++) {
        atomicAdd(&sRow[erow[mt]], sA[mt]);
        atomicAdd(&qRow[erow[mt]], qA[mt]);
    }
    __syncthreads();
    if (tid < 128) {
        atomicAdd(&g_s3[bx * 128 + tid], sRow[tid]);
        atomicAdd(&g_q3[bx * 128 + tid], qRow[tid]);
    }
}

// ---------------- K3F: finalize LN3 stats ----------------
__global__ void k3f_final() {
    int b = blockIdx.x * 256 + threadIdx.x;
    float mu = g_s3[b] / 32768.f;
    g_mu3[b] = mu;
    g_rs3[b] = rsqrtf(g_q3[b] / 32768.f - mu * mu + 1e-12f);
}

// ---------------- K4: relu(LN3) -> conv(HMMA) -> +bc -> tanh -> out ----------------
__global__ void __launch_bounds__(256, 2)
k4_out(const float* __restrict__ g3, const float* __restrict__ b3,
       const float* __restrict__ bc, float* __restrict__ out) {
    __shared__ __align__(16) char sm4[32768];    // A 16K | B 2x8K
    __shared__ float g3s[1024], b3s[1024];
    uint32_t s32 = smem_to_u32(sm4);

    int tid = threadIdx.x;
    int wid = tid >> 5, lid = tid & 31;
    int bx = blockIdx.x;
    int wm = wid & 3, wn = wid >> 2;
    int l2 = lid & 3;

    #pragma unroll
    for (int i = 0; i < 4; i++) { g3s[tid + i * 256] = g3[tid + i * 256]; b3s[tid + i * 256] = b3[tid + i * 256]; }

    int rowL = tid >> 3, cl = tid & 7;
    float amus[4], arss[4];
    uint32_t aSts[4];
    #pragma unroll
    for (int it = 0; it < 4; it++) {
        int r = rowL + it * 32;
        int bat = (bx * 128 + r) >> 5;
        amus[it] = g_mu3[bat];
        arss[it] = g_rs3[bat];
        aSts[it] = SW128((uint32_t)(r * 128 + cl * 16));
    }
    __syncthreads();

    uint32_t swB[2]; int bofs[2];
    #pragma unroll
    for (int i = 0; i < 2; i++) {
        int idx = tid + i * 256;
        int row = idx >> 3, q = idx & 7;
        swB[i] = SW128((uint32_t)(row * 128 + q * 16));
        bofs[i] = row * 1024 + q * 8;
    }

    int lar = (lid & 7) + ((lid >> 3) & 1) * 8;
    int lac2 = ((lid >> 4) & 1) * 16;
    int lbr = (lid & 7) + ((lid >> 4) & 1) * 8;
    int lbc2 = ((lid >> 3) & 1) * 16;
    uint32_t aBase[2], aXor[2], bBase[2], bXor[2];
    #pragma unroll
    for (int mt = 0; mt < 2; mt++) {
        int r = wm * 32 + mt * 16 + lar;
        aBase[mt] = (uint32_t)(r * 128);
        aXor[mt] = (uint32_t)((r & 7) << 4);
    }
    #pragma unroll
    for (int np = 0; np < 2; np++) {
        int r = wn * 32 + np * 16 + lbr;
        bBase[np] = (uint32_t)(r * 128);
        bXor[np] = (uint32_t)((r & 7) << 4);
    }

    float acc[2][4][4];
    #pragma unroll
    for (int mt = 0; mt < 2; mt++)
        #pragma unroll
        for (int nt = 0; nt < 4; nt++)
            #pragma unroll
            for (int j = 0; j < 4; j++) acc[mt][nt][j] = 0.f;

    uint4 regA[4];
    auto doLoadA = [&](int kc) {
        float4 gg0 = *(const float4*)&g3s[kc * 64 + cl * 8];
        float4 gg1 = *(const float4*)&g3s[kc * 64 + cl * 8 + 4];
        float4 bb0 = *(const float4*)&b3s[kc * 64 + cl * 8];
        float4 bb1 = *(const float4*)&b3s[kc * 64 + cl * 8 + 4];
        #pragma unroll
        for (int it = 0; it < 4; it++) {
            int r = rowL + it * 32;
            uint4 v = *(const uint4*)(g_hcatH + (size_t)(bx * 128 + r) * (2 * HH) + kc * 64 + cl * 8);
            const __half* hv = (const __half*)&v;
            float amu = amus[it], ars = arss[it];
            uint4 o;
            __half* ho = (__half*)&o;
            ho[0] = __float2half(fmaxf((__half2float(hv[0]) - amu) * ars * gg0.x + bb0.x, 0.f));
            ho[1] = __float2half(fmaxf((__half2float(hv[1]) - amu) * ars * gg0.y + bb0.y, 0.f));
            ho[2] = __float2half(fmaxf((__half2float(hv[2]) - amu) * ars * gg0.z + bb0.z, 0.f));
            ho[3] = __float2half(fmaxf((__half2float(hv[3]) - amu) * ars * gg0.w + bb0.w, 0.f));
            ho[4] = __float2half(fmaxf((__half2float(hv[4]) - amu) * ars * gg1.x + bb1.x, 0.f));
            ho[5] = __float2half(fmaxf((__half2float(hv[5]) - amu) * ars * gg1.y + bb1.y, 0.f));
            ho[6] = __float2half(fmaxf((__half2float(hv[6]) - amu) * ars * gg1.z + bb1.z, 0.f));
            ho[7] = __float2half(fmaxf((__half2float(hv[7]) - amu) * ars * gg1.w + bb1.w, 0.f));
            regA[it] = o;
        }
    };
    auto doStsA = [&]() {
        #pragma unroll
        for (int it = 0; it < 4; it++)
            *(uint4*)(sm4 + aSts[it]) = regA[it];
    };
    auto doCpaB = [&](int kc, int st) {
        uint32_t sb = s32 + 16384 + (uint32_t)st * 8192u;
        #pragma unroll
        for (int i = 0; i < 2; i++)
            cpa16(sb + swB[i], g_wch + bofs[i] + kc * 64);
        CP_COMMIT();
    };

    doLoadA(0);
    doCpaB(0, 0);
    int st = 0;

    #pragma unroll 1
    for (int kc = 0; kc < 16; kc++) {
        __syncthreads();
        if (kc < 15) doCpaB(kc + 1, st ^ 1);
        if (kc < 15) { CP_WAIT(1); } else { CP_WAIT(0); }
        doStsA();
        if (kc < 15) doLoadA(kc + 1);
        __syncthreads();

        uint32_t bS = s32 + 16384 + (uint32_t)st * 8192u;
        #pragma unroll
        for (int kt = 0; kt < 4; kt++) {
            uint32_t ah[2][4], bf[2][4];
            #pragma unroll
            for (int mt = 0; mt < 2; mt++) {
                uint32_t cb = ((uint32_t)(kt * 32 + lac2)) ^ aXor[mt];
                ldsm4(ah[mt], s32 + aBase[mt] + cb);
            }
            #pragma unroll
            for (int np = 0; np < 2; np++) {
                uint32_t cb = ((uint32_t)(kt * 32 + lbc2)) ^ bXor[np];
                ldsm4(bf[np], bS + bBase[np] + cb);
            }
            #pragma unroll
            for (int mt = 0; mt < 2; mt++)
                #pragma unroll
                for (int nt = 0; nt < 4; nt++)
                    mma16816h(acc[mt][nt], ah[mt], &bf[nt >> 1][(nt & 1) * 2]);
        }
        st ^= 1;
    }

    #pragma unroll
    for (int mt = 0; mt < 2; mt++) {
        int r = wm * 32 + mt * 16 + (lid >> 2);
        int gr = bx * 128 + r;
        #pragma unroll
        for (int nt = 0; nt < 4; nt++) {
            int c = wn * 32 + nt * 8 + l2 * 2;
            float b0 = bc[c], b1v = bc[c + 1];
            float2 v0 = make_float2(ftanh(acc[mt][nt][0] + b0), ftanh(acc[mt][nt][1] + b1v));
            float2 v1 = make_float2(ftanh(acc[mt][nt][2] + b0), ftanh(acc[mt][nt][3] + b1v));
            *(float2*)(out + (size_t)gr * AA + c) = v0;
            *(float2*)(out + (size_t)(gr + 8) * AA + c) = v1;
        }
    }
}

// ---------------- launch ----------------
extern "C" void kernel_launch(void* const* d_in, const int* in_sizes, int n_in,
                              void* d_out, int out_size) {
    int s = (n_in >= 18) ? 1 : 0;
    const float* ud  = (const float*)d_in[0];
    const int*   au  = (const int*)  d_in[2];
    const float* g1  = (const float*)d_in[3 + s];
    const float* b1  = (const float*)d_in[4 + s];
    const float* Wd  = (const float*)d_in[5 + s];
    const float* bd  = (const float*)d_in[6 + s];
    const float* g2  = (const float*)d_in[7 + s];
    const float* b2  = (const float*)d_in[8 + s];
    const float* Wfw = (const float*)d_in[9 + s];
    const float* bfw = (const float*)d_in[10 + s];
    const float* Wbw = (const float*)d_in[11 + s];
    const float* bbw = (const float*)d_in[12 + s];
    const float* g3  = (const float*)d_in[13 + s];
    const float* b3  = (const float*)d_in[14 + s];
    const float* Wc  = (const float*)d_in[15 + s];
    const float* bc  = (const float*)d_in[16 + s];
    float* out = (float*)d_out;

    const int K2_SMEM = 1024 + 3 * 49152 + 66048 + 17408;   // 231936 bytes
    cudaFuncSetAttribute(k2p_persist, cudaFuncAttributeMaxDynamicSharedMemorySize, K2_SMEM);

    kp_w<<<(2 * KIN * G4) / 256, 256>>>(Wfw, Wbw);
    kp_dc<<<512, 256>>>(Wd, Wc);
    k1_dense<<<BT / 128, 256>>>(ud, g1, b1, bd, g2, b2);
    k2p_persist<<<dim3(16, 4, 2), 256, K2_SMEM>>>(bfw, bbw, au);
    k3f_final<<<BB / 256, 256>>>();
    k4_out<<<BT / 128, 256>>>(g3, b3, bc, out);
}

// round 17
// speedup vs baseline: 1.1049x; 1.0012x over previous
#include <cuda_runtime.h>
#include <cuda_fp16.h>
#include <math.h>
#include <stdint.h>

// Problem constants
#define BB   2048
#define TT   32
#define BT   65536        // BB*TT
#define DIN_ 1024
#define DH_  64
#define HH   512
#define G4   2048         // 4*H
#define KIN  576          // DH + H
#define AA   64

typedef unsigned long long u64;

#define SW128(off) ((off) ^ (((off) >> 3) & 0x70))

// ======================= helpers =======================
__device__ __forceinline__ uint32_t smem_to_u32(const void* p) {
    uint32_t a;
    asm("{ .reg .u64 t; cvta.to.shared.u64 t, %1; cvt.u32.u64 %0, t; }" : "=r"(a) : "l"(p));
    return a;
}
__device__ __forceinline__ void cpa16(uint32_t s, const void* g) {
    asm volatile("cp.async.cg.shared.global [%0], [%1], 16;" :: "r"(s), "l"(g));
}
#define CP_COMMIT() asm volatile("cp.async.commit_group;" ::: "memory")
#define CP_WAIT(n)  asm volatile("cp.async.wait_group %0;" :: "n"(n) : "memory")
__device__ __forceinline__ void ldsm4(uint32_t* r, uint32_t addr) {
    asm volatile("ldmatrix.sync.aligned.m8n8.x4.shared.b16 {%0,%1,%2,%3}, [%4];"
        : "=r"(r[0]), "=r"(r[1]), "=r"(r[2]), "=r"(r[3]) : "r"(addr));
}
__device__ __forceinline__ void mma16816h(float* c, const uint32_t* a, const uint32_t* b) {
    asm volatile("mma.sync.aligned.m16n8k16.row.col.f32.f16.f16.f32 "
        "{%0,%1,%2,%3}, {%4,%5,%6,%7}, {%8,%9}, {%0,%1,%2,%3};"
        : "+f"(c[0]), "+f"(c[1]), "+f"(c[2]), "+f"(c[3])
        : "r"(a[0]), "r"(a[1]), "r"(a[2]), "r"(a[3]), "r"(b[0]), "r"(b[1]));
}
// fast gates
__device__ __forceinline__ float tapx(float x) {
    float y; asm("tanh.approx.f32 %0, %1;" : "=f"(y) : "f"(x)); return y;
}
__device__ __forceinline__ float sigax(float x) { return fmaf(tapx(0.5f * x), 0.5f, 0.5f); }
// accurate-ish tanh for final output
__device__ __forceinline__ float ftanh(float x) { return 1.f - __fdividef(2.f, __expf(2.f * x) + 1.f); }

#define CLUSTER_ARRIVE() asm volatile("barrier.cluster.arrive.aligned;" ::: "memory")
#define CLUSTER_WAIT()   asm volatile("barrier.cluster.wait.aligned;" ::: "memory")

// ======================= scratch (device globals) =======================
__device__ __half g_xph[BT * DH_];               // x (fp16)  [(b*T+t)*64+d]
__device__ __half g_wph[2][8][256 * 576];        // LSTM W [dir][nb][n'(256)*576+k], n'=nl*4+gate
__device__ __half g_wdh[64 * 1024];              // Wd^T  [n(64)][k(1024)]
__device__ __half g_wch[64 * 1024];              // Wc^T  [a(64)][h(1024)]
__device__ float  g_swd[64];                     // g1 @ Wd
__device__ float  g_sbd[64];                     // b1 @ Wd
__device__ __half g_hh[2][2][BB * HH];           // [dir][buf][b*512+n]
__device__ __half g_hcatH[BT * 2 * HH];          // [b][t][1024] masked, bw at reversed t
__device__ float g_s3[BB];                       // LN3 partial sums (zeroed by kp_w)
__device__ float g_q3[BB];
__device__ float g_mu3[BB];
__device__ float g_rs3[BB];

// ---------------- KP: prepack LSTM W into fp16, gate-interleaved, K-major (+ zero LN3 partials) ----------------
__global__ void kp_w(const float* __restrict__ Wfw, const float* __restrict__ Wbw) {
    int idx = blockIdx.x * 256 + threadIdx.x;    // 2 * 576 * 2048 total
    if (idx < BB) { g_s3[idx] = 0.f; g_q3[idx] = 0.f; }
    int dir = idx >= (KIN * G4);
    int r = idx - dir * (KIN * G4);
    int k = r >> 11;
    int col = r & 2047;
    const float* W = dir ? Wbw : Wfw;
    float v = W[(size_t)k * G4 + col];
    int g = col >> 9, rr = col & 511, nb = rr >> 6, nl = rr & 63;
    int np = nl * 4 + g;
    g_wph[dir][nb][np * 576 + k] = __float2half(v);
}

// ---------------- KP2: transpose-pack Wd/Wc to fp16 [n][k] + swd/sbd correction vectors ----------------
__global__ void kp_dc(const float* __restrict__ Wd, const float* __restrict__ Wc,
                      const float* __restrict__ g1, const float* __restrict__ b1) {
    int idx = blockIdx.x * 256 + threadIdx.x;    // 2 * 65536
    int which = idx >= 65536;
    int r = idx & 65535;
    int k = r >> 6, n = r & 63;
    if (!which) g_wdh[n * 1024 + k] = __float2half(Wd[(size_t)k * 64 + n]);
    else        g_wch[n * 1024 + k] = __float2half(Wc[(size_t)k * 64 + n]);
    if (blockIdx.x == 0 && threadIdx.x < 128) {
        int c = threadIdx.x & 63;
        bool doB = threadIdx.x >= 64;
        const float* vv = doB ? b1 : g1;
        float s = 0.f;
        for (int kk = 0; kk < 1024; kk++) s += vv[kk] * Wd[(size_t)kk * 64 + c];
        if (doB) g_sbd[c] = s; else g_swd[c] = s;
    }
}

// ---------------- K1: single-pass dense — GEMM on (x.*g1), LN1 via algebraic correction ----------------
// grid 512, 256 threads (8 warps: 4m x 2n), CTA tile 128x64, K=1024 in 16 chunks of 64.
// z = rs*P - rs*mu*swd[c] + (sbd[c] + bd[c]) ; then LN2 -> relu -> fp16.
__global__ void __launch_bounds__(256, 2)
k1_dense(const float* __restrict__ ud,
         const float* __restrict__ g1,
         const float* __restrict__ bd,
         const float* __restrict__ g2, const float* __restrict__ b2) {
    __shared__ __align__(16) char sm1[33792];    // A 16K | B 2x8K ; buf f32[128][65] aliases
    __shared__ float g1s[1024];
    __shared__ float swds[64], cadds[64];
    __shared__ float smuA[128], srsA[128];       // LN1 row stats (from fused accumulation)
    __shared__ float smu[128], srs[128];         // LN2 row stats
    uint32_t s32 = smem_to_u32(sm1);
    float* buf = (float*)sm1;

    int tid = threadIdx.x;
    int wid = tid >> 5, lid = tid & 31;
    int bx = blockIdx.x;
    int wm = wid & 3, wn = wid >> 2;
    int l2 = lid & 3;

    #pragma unroll
    for (int i = 0; i < 4; i++) g1s[tid + i * 256] = g1[tid + i * 256];
    if (tid < 64) { swds[tid] = g_swd[tid]; cadds[tid] = g_sbd[tid] + bd[tid]; }
    __syncthreads();

    // A mapping: 8 lanes/row (16B each half-row), 4 rows/thread
    int rowL = tid >> 3, cl = tid & 7;
    uint32_t aSts[4];
    #pragma unroll
    for (int it = 0; it < 4; it++)
        aSts[it] = SW128((uint32_t)((rowL + it * 32) * 128 + cl * 16));

    float sP[4] = {0.f, 0.f, 0.f, 0.f}, qP[4] = {0.f, 0.f, 0.f, 0.f};

    uint32_t swB[2]; int bofs[2];
    #pragma unroll
    for (int i = 0; i < 2; i++) {
        int idx = tid + i * 256;
        int row = idx >> 3, q = idx & 7;
        swB[i] = SW128((uint32_t)(row * 128 + q * 16));
        bofs[i] = row * 1024 + q * 8;
    }

    int lar = (lid & 7) + ((lid >> 3) & 1) * 8;
    int lac2 = ((lid >> 4) & 1) * 16;
    int lbr = (lid & 7) + ((lid >> 4) & 1) * 8;
    int lbc2 = ((lid >> 3) & 1) * 16;
    uint32_t aBase[2], aXor[2], bBase[2], bXor[2];
    #pragma unroll
    for (int mt = 0; mt < 2; mt++) {
        int r = wm * 32 + mt * 16 + lar;
        aBase[mt] = (uint32_t)(r * 128);
        aXor[mt] = (uint32_t)((r & 7) << 4);
    }
    #pragma unroll
    for (int np = 0; np < 2; np++) {
        int r = wn * 32 + np * 16 + lbr;
        bBase[np] = (uint32_t)(r * 128);
        bXor[np] = (uint32_t)((r & 7) << 4);
    }

    float acc[2][4][4];
    #pragma unroll
    for (int mt = 0; mt < 2; mt++)
        #pragma unroll
        for (int nt = 0; nt < 4; nt++)
            #pragma unroll
            for (int j = 0; j < 4; j++) acc[mt][nt][j] = 0.f;

    uint4 regA[4];
    auto doLoadA = [&](int kc) {
        float4 gg0 = *(const float4*)&g1s[kc * 64 + cl * 8];
        float4 gg1 = *(const float4*)&g1s[kc * 64 + cl * 8 + 4];
        #pragma unroll
        for (int it = 0; it < 4; it++) {
            int r = rowL + it * 32;
            const float* src = ud + (size_t)(bx * 128 + r) * DIN_ + kc * 64 + cl * 8;
            float4 v0 = *(const float4*)src;
            float4 v1 = *(const float4*)(src + 4);
            sP[it] += (v0.x + v0.y + v0.z + v0.w) + (v1.x + v1.y + v1.z + v1.w);
            qP[it] += v0.x * v0.x + v0.y * v0.y + v0.z * v0.z + v0.w * v0.w
                    + v1.x * v1.x + v1.y * v1.y + v1.z * v1.z + v1.w * v1.w;
            uint4 o;
            __half* ho = (__half*)&o;
            ho[0] = __float2half(v0.x * gg0.x);
            ho[1] = __float2half(v0.y * gg0.y);
            ho[2] = __float2half(v0.z * gg0.z);
            ho[3] = __float2half(v0.w * gg0.w);
            ho[4] = __float2half(v1.x * gg1.x);
            ho[5] = __float2half(v1.y * gg1.y);
            ho[6] = __float2half(v1.z * gg1.z);
            ho[7] = __float2half(v1.w * gg1.w);
            regA[it] = o;
        }
    };
    auto doStsA = [&]() {
        #pragma unroll
        for (int it = 0; it < 4; it++)
            *(uint4*)(sm1 + aSts[it]) = regA[it];
    };
    auto doCpaB = [&](int kc, int st) {
        uint32_t sb = s32 + 16384 + (uint32_t)st * 8192u;
        #pragma unroll
        for (int i = 0; i < 2; i++)
            cpa16(sb + swB[i], g_wdh + bofs[i] + kc * 64);
        CP_COMMIT();
    };

    doLoadA(0);
    doCpaB(0, 0);
    int st = 0;

    #pragma unroll 1
    for (int kc = 0; kc < 16; kc++) {
        __syncthreads();
        if (kc < 15) doCpaB(kc + 1, st ^ 1);
        if (kc < 15) { CP_WAIT(1); } else { CP_WAIT(0); }
        doStsA();
        if (kc < 15) doLoadA(kc + 1);
        __syncthreads();

        uint32_t bS = s32 + 16384 + (uint32_t)st * 8192u;
        #pragma unroll
        for (int kt = 0; kt < 4; kt++) {
            uint32_t ah[2][4], bf[2][4];
            #pragma unroll
            for (int mt = 0; mt < 2; mt++) {
                uint32_t cb = ((uint32_t)(kt * 32 + lac2)) ^ aXor[mt];
                ldsm4(ah[mt], s32 + aBase[mt] + cb);
            }
            #pragma unroll
            for (int np = 0; np < 2; np++) {
                uint32_t cb = ((uint32_t)(kt * 32 + lbc2)) ^ bXor[np];
                ldsm4(bf[np], bS + bBase[np] + cb);
            }
            #pragma unroll
            for (int mt = 0; mt < 2; mt++)
                #pragma unroll
                for (int nt = 0; nt < 4; nt++)
                    mma16816h(acc[mt][nt], ah[mt], &bf[nt >> 1][(nt & 1) * 2]);
        }
        st ^= 1;
    }

    // ---- reduce fused LN1 stats across the 8 lanes of each row ----
    #pragma unroll
    for (int it = 0; it < 4; it++) {
        #pragma unroll
        for (int o = 1; o < 8; o <<= 1) {
            sP[it] += __shfl_xor_sync(0xffffffffu, sP[it], o);
            qP[it] += __shfl_xor_sync(0xffffffffu, qP[it], o);
        }
    }
    if (cl == 0) {
        #pragma unroll
        for (int it = 0; it < 4; it++) {
            int r = rowL + it * 32;
            float mu = sP[it] / 1024.f;
            smuA[r] = mu;
            srsA[r] = rsqrtf(qP[it] / 1024.f - mu * mu + 1e-12f);
        }
    }
    __syncthreads();   // all MMA done + stats ready; smem now reused as buf

    // ---- stage z with LN1 correction: z = rs*P - rs*mu*swd + cadd ----
    #pragma unroll
    for (int mt = 0; mt < 2; mt++) {
        int r = wm * 32 + mt * 16 + (lid >> 2);
        float mu0 = smuA[r], rs0 = srsA[r];
        float mu1 = smuA[r + 8], rs1 = srsA[r + 8];
        #pragma unroll
        for (int nt = 0; nt < 4; nt++) {
            int c = wn * 32 + nt * 8 + l2 * 2;
            float w0 = swds[c], w1 = swds[c + 1];
            float c0 = cadds[c], c1 = cadds[c + 1];
            buf[r * 65 + c]           = rs0 * (acc[mt][nt][0] - mu0 * w0) + c0;
            buf[r * 65 + c + 1]       = rs0 * (acc[mt][nt][1] - mu0 * w1) + c1;
            buf[(r + 8) * 65 + c]     = rs1 * (acc[mt][nt][2] - mu1 * w0) + c0;
            buf[(r + 8) * 65 + c + 1] = rs1 * (acc[mt][nt][3] - mu1 * w1) + c1;
        }
    }
    __syncthreads();

    if (tid < 128) {
        float s = 0.f, q = 0.f;
        #pragma unroll
        for (int c = 0; c < 64; c++) { float v = buf[tid * 65 + c]; s += v; q += v * v; }
        float mu = s / 64.f;
        smu[tid] = mu;
        srs[tid] = rsqrtf(q / 64.f - mu * mu + 1e-12f);
    }
    __syncthreads();

    int ty = tid >> 4, tx = tid & 15;
    #pragma unroll
    for (int r = 0; r < 8; r++) {
        int lr = ty * 8 + r;
        float mu = smu[lr], rs = srs[lr];
        int gr = bx * 128 + lr;
        #pragma unroll
        for (int j = 0; j < 4; j++) {
            int c = tx * 4 + j;
            float y = (buf[lr * 65 + c] - mu) * rs * g2[c] + b2[c];
            g_xph[(size_t)gr * DH_ + c] = __float2half(fmaxf(y, 0.f));
        }
    }
}

// ---------------- K2P: persistent bidirectional LSTM (cluster-per-group, fused LN3 partials) ----------------
__global__ void __launch_bounds__(256, 1) __cluster_dims__(1, 4, 1)
k2p_persist(const float* __restrict__ bfw, const float* __restrict__ bbw,
            const int* __restrict__ au) {
    extern __shared__ __align__(16) char dsm[];

    int tid = threadIdx.x;
    int wid = tid >> 5, lid = tid & 31;
    int bx = blockIdx.x, npair = blockIdx.y, dir = blockIdx.z;
    int wm = wid >> 2, wn = wid & 3;          // warp grid 2m x 4n

    uint32_t b32 = smem_to_u32(dsm);
    uint32_t tb32 = (b32 + 1023) & ~1023u;
    char* tb = dsm + (tb32 - b32);
    float* cS = (float*)(tb + 147456);            // c-state [128][129] f32
    char*  hst = tb + 147456 + 66048;             // h-stage [128][68] fp16

    const float* bias = dir ? bbw : bfw;

    uint32_t swA[4]; int gbA[4], qA8[4], aA[4];
    #pragma unroll
    for (int i = 0; i < 4; i++) {
        int idx = tid + i * 256;
        int row = idx >> 3, q = idx & 7;
        swA[i] = SW128((uint32_t)(row * 128 + q * 16));
        gbA[i] = bx * 128 + row;
        qA8[i] = q * 8;
        aA[i] = au[gbA[i]];
    }
    uint32_t swB[8]; int boff[8];
    #pragma unroll
    for (int i = 0; i < 8; i++) {
        int idx = tid + i * 256;
        int row = idx >> 3, q = idx & 7;
        swB[i] = SW128((uint32_t)(row * 128 + q * 16));
        boff[i] = row * KIN + q * 8;
    }

    int lar = (lid & 7) + ((lid >> 3) & 1) * 8;
    int lac2 = ((lid >> 4) & 1) * 16;
    int lbr = (lid & 7) + ((lid >> 4) & 1) * 8;
    int lbc2 = ((lid >> 3) & 1) * 16;
    uint32_t aBase[4], aXor[4], bBase[4], bXor[4];
    #pragma unroll
    for (int mt = 0; mt < 4; mt++) {
        int r = wm * 64 + mt * 16 + lar;
        aBase[mt] = (uint32_t)(r * 128);
        aXor[mt] = (uint32_t)((r & 7) << 4);
    }
    #pragma unroll
    for (int np = 0; np < 4; np++) {
        int r = wn * 64 + np * 16 + lbr;
        bBase[np] = (uint32_t)(r * 128);
        bXor[np] = (uint32_t)((r & 7) << 4);
    }

    int l2 = lid & 3;
    int erow[4], eau[4];
    float sA[4], qA[4];
    #pragma unroll
    for (int mt = 0; mt < 4; mt++) {
        erow[mt] = wm * 64 + mt * 16 + (lid >> 2) + (l2 & 1) * 8;
        eau[mt] = au[bx * 128 + erow[mt]];
        sA[mt] = 0.f; qA[mt] = 0.f;
    }

    float acc[4][8][4];
    #pragma unroll
    for (int mt = 0; mt < 4; mt++)
        #pragma unroll
        for (int nt = 0; nt < 8; nt++)
            #pragma unroll
            for (int j = 0; j < 4; j++) acc[mt][nt][j] = 0.f;

    int sbuf = 0, cbuf = 0;

    auto issueC = [&](int t, int ci) {
        int NC = (t == 0) ? 1 : 9;
        int half = (ci >= NC) ? 1 : 0;
        int kc = ci - half * NC;
        uint32_t sb = tb32 + (uint32_t)sbuf * 49152u;
        if (kc == 0) {
            #pragma unroll
            for (int i = 0; i < 4; i++) {
                int ts = t;
                if (dir) ts = (t < aA[i]) ? (aA[i] - 1 - t) : t;
                cpa16(sb + swA[i], g_xph + (gbA[i] * TT + ts) * DH_ + qA8[i]);
            }
        } else {
            const __half* hp = g_hh[dir][(t & 1) ^ 1];
            int e0 = (kc - 1) * 64;
            #pragma unroll
            for (int i = 0; i < 4; i++)
                cpa16(sb + swA[i], hp + gbA[i] * HH + e0 + qA8[i]);
        }
        int nb = npair * 2 + half;
        const __half* wp = g_wph[dir][nb];
        int ke = kc * 64;
        #pragma unroll
        for (int i = 0; i < 8; i++)
            cpa16(sb + 16384 + swB[i], wp + boff[i] + ke);
        CP_COMMIT();
        sbuf = (sbuf == 2) ? 0 : sbuf + 1;
    };

    int pending = 0;

    #pragma unroll 1
    for (int t = 0; t < TT; t++) {
        int NC = (t == 0) ? 1 : 9;
        int NC2 = 2 * NC;

        int issued = pending;
        while (issued < NC2 && issued < 2) { issueC(t, issued); issued++; }

        #pragma unroll 1
        for (int ci = 0; ci < NC2; ci++) {
            if (issued - ci >= 2) CP_WAIT(1);
            else                  CP_WAIT(0);
            __syncthreads();
            if (issued < NC2) { issueC(t, issued); issued++; }

            uint32_t sb = tb32 + (uint32_t)cbuf * 49152u;
            cbuf = (cbuf == 2) ? 0 : cbuf + 1;

            #pragma unroll
            for (int kt = 0; kt < 4; kt++) {
                uint32_t ah[4][4], bf[4][4];
                #pragma unroll
                for (int mt = 0; mt < 4; mt++) {
                    uint32_t cb = ((uint32_t)(kt * 32 + lac2)) ^ aXor[mt];
                    ldsm4(ah[mt], sb + aBase[mt] + cb);
                }
                #pragma unroll
                for (int np = 0; np < 4; np++) {
                    uint32_t cb = ((uint32_t)(kt * 32 + lbc2)) ^ bXor[np];
                    ldsm4(bf[np], sb + 16384 + bBase[np] + cb);
                }
                #pragma unroll
                for (int mt = 0; mt < 4; mt++)
                    #pragma unroll
                    for (int nt = 0; nt < 8; nt++)
                        mma16816h(acc[mt][nt], ah[mt], &bf[nt >> 1][(nt & 1) * 2]);
            }

            if (ci == NC - 1 || ci == NC2 - 1) {
                int half = (ci >= NC) ? 1 : 0;
                int nb = npair * 2 + half;
                bool oddl = (l2 & 1);
                #pragma unroll
                for (int mt = 0; mt < 4; mt++) {
                    int row = erow[mt];
                    bool m = (t < eau[mt]);
                    #pragma unroll
                    for (int nt = 0; nt < 8; nt++) {
                        float o0 = acc[mt][nt][0], o1 = acc[mt][nt][1];
                        float o2 = acc[mt][nt][2], o3 = acc[mt][nt][3];
                        float r0 = __shfl_xor_sync(0xffffffffu, o0, 1);
                        float r1 = __shfl_xor_sync(0xffffffffu, o1, 1);
                        float r2 = __shfl_xor_sync(0xffffffffu, o2, 1);
                        float r3 = __shfl_xor_sync(0xffffffffu, o3, 1);
                        float zi, zj, zf, zo;
                        if (!oddl) { zi = o0; zj = o1; zf = r0; zo = r1; }
                        else       { zi = r2; zj = r3; zf = o2; zo = o3; }
                        int u = wn * 16 + nt * 2 + (l2 >> 1);
                        int n = nb * 64 + u;
                        float vi = zi + bias[n];
                        float vj = zj + bias[HH + n];
                        float vf = zf + bias[2 * HH + n];
                        float vo = zo + bias[3 * HH + n];
                        int cidx = row * 129 + half * 64 + u;
                        float cp = (t == 0) ? 0.f : cS[cidx];
                        float cn = cp * sigax(vf + 1.0f) + sigax(vi) * tapx(vj);
                        float hn = tapx(cn) * sigax(vo);
                        cS[cidx] = cn;
                        *(__half*)(hst + (row * 68 + u) * 2) = __float2half(hn);
                        float hv = m ? hn : 0.f;
                        sA[mt] += hv;
                        qA[mt] = fmaf(hv, hv, qA[mt]);
                    }
                }
                #pragma unroll
                for (int mt = 0; mt < 4; mt++)
                    #pragma unroll
                    for (int nt = 0; nt < 8; nt++)
                        #pragma unroll
                        for (int j = 0; j < 4; j++) acc[mt][nt][j] = 0.f;

                __syncthreads();
                __half* oh = g_hh[dir][t & 1];
                #pragma unroll
                for (int i = 0; i < 8; i++) {
                    int idx = tid + i * 256;
                    int row = idx >> 4, ch = idx & 15;
                    u64 v = *(const u64*)(hst + row * 136 + ch * 8);
                    *(u64*)((char*)oh + ((size_t)(bx * 128 + row) * HH + nb * 64 + ch * 4) * 2) = v;
                }
                #pragma unroll
                for (int i = 0; i < 8; i++) {
                    int idx = tid + i * 256;
                    int row = idx >> 4, ch = idx & 15;
                    int gb = bx * 128 + row;
                    int a0 = au[gb];
                    u64 v = *(const u64*)(hst + row * 136 + ch * 8);
                    int ts;
                    if (t < a0) ts = dir ? (a0 - 1 - t) : t;
                    else { ts = t; v = 0ull; }
                    *(u64*)((char*)g_hcatH +
                        (((size_t)gb * TT + ts) * (2 * HH) + dir * HH + nb * 64 + ch * 4) * 2) = v;
                }
            }
        }

        if (t < TT - 1) {
            issueC(t + 1, 0);
            pending = 1;
            CLUSTER_ARRIVE();
            CLUSTER_WAIT();
        }
    }

    // ---- end: reduce fused LN3 partials and add to global ----
    float* sRow = (float*)tb;
    float* qRow = (float*)(tb + 512);
    if (tid < 128) { sRow[tid] = 0.f; qRow[tid] = 0.f; }
    __syncthreads();
    #pragma unroll
    for (int mt = 0; mt < 4; mt++) {
        atomicAdd(&sRow[erow[mt]], sA[mt]);
        atomicAdd(&qRow[erow[mt]], qA[mt]);
    }
    __syncthreads();
    if (tid < 128) {
        atomicAdd(&g_s3[bx * 128 + tid], sRow[tid]);
        atomicAdd(&g_q3[bx * 128 + tid], qRow[tid]);
    }
}

// ---------------- K3F: finalize LN3 stats ----------------
__global__ void k3f_final() {
    int b = blockIdx.x * 256 + threadIdx.x;
    float mu = g_s3[b] / 32768.f;
    g_mu3[b] = mu;
    g_rs3[b] = rsqrtf(g_q3[b] / 32768.f - mu * mu + 1e-12f);
}

// ---------------- K4: relu(LN3) -> conv(HMMA) -> +bc -> tanh -> out ----------------
__global__ void __launch_bounds__(256, 2)
k4_out(const float* __restrict__ g3, const float* __restrict__ b3,
       const float* __restrict__ bc, float* __restrict__ out) {
    __shared__ __align__(16) char sm4[32768];    // A 16K | B 2x8K
    __shared__ float g3s[1024], b3s[1024];
    uint32_t s32 = smem_to_u32(sm4);

    int tid = threadIdx.x;
    int wid = tid >> 5, lid = tid & 31;
    int bx = blockIdx.x;
    int wm = wid & 3, wn = wid >> 2;
    int l2 = lid & 3;

    #pragma unroll
    for (int i = 0; i < 4; i++) { g3s[tid + i * 256] = g3[tid + i * 256]; b3s[tid + i * 256] = b3[tid + i * 256]; }

    int rowL = tid >> 3, cl = tid & 7;
    float amus[4], arss[4];
    uint32_t aSts[4];
    #pragma unroll
    for (int it = 0; it < 4; it++) {
        int r = rowL + it * 32;
        int bat = (bx * 128 + r) >> 5;
        amus[it] = g_mu3[bat];
        arss[it] = g_rs3[bat];
        aSts[it] = SW128((uint32_t)(r * 128 + cl * 16));
    }
    __syncthreads();

    uint32_t swB[2]; int bofs[2];
    #pragma unroll
    for (int i = 0; i < 2; i++) {
        int idx = tid + i * 256;
        int row = idx >> 3, q = idx & 7;
        swB[i] = SW128((uint32_t)(row * 128 + q * 16));
        bofs[i] = row * 1024 + q * 8;
    }

    int lar = (lid & 7) + ((lid >> 3) & 1) * 8;
    int lac2 = ((lid >> 4) & 1) * 16;
    int lbr = (lid & 7) + ((lid >> 4) & 1) * 8;
    int lbc2 = ((lid >> 3) & 1) * 16;
    uint32_t aBase[2], aXor[2], bBase[2], bXor[2];
    #pragma unroll
    for (int mt = 0; mt < 2; mt++) {
        int r = wm * 32 + mt * 16 + lar;
        aBase[mt] = (uint32_t)(r * 128);
        aXor[mt] = (uint32_t)((r & 7) << 4);
    }
    #pragma unroll
    for (int np = 0; np < 2; np++) {
        int r = wn * 32 + np * 16 + lbr;
        bBase[np] = (uint32_t)(r * 128);
        bXor[np] = (uint32_t)((r & 7) << 4);
    }

    float acc[2][4][4];
    #pragma unroll
    for (int mt = 0; mt < 2; mt++)
        #pragma unroll
        for (int nt = 0; nt < 4; nt++)
            #pragma unroll
            for (int j = 0; j < 4; j++) acc[mt][nt][j] = 0.f;

    uint4 regA[4];
    auto doLoadA = [&](int kc) {
        float4 gg0 = *(const float4*)&g3s[kc * 64 + cl * 8];
        float4 gg1 = *(const float4*)&g3s[kc * 64 + cl * 8 + 4];
        float4 bb0 = *(const float4*)&b3s[kc * 64 + cl * 8];
        float4 bb1 = *(const float4*)&b3s[kc * 64 + cl * 8 + 4];
        #pragma unroll
        for (int it = 0; it < 4; it++) {
            int r = rowL + it * 32;
            uint4 v = *(const uint4*)(g_hcatH + (size_t)(bx * 128 + r) * (2 * HH) + kc * 64 + cl * 8);
            const __half* hv = (const __half*)&v;
            float amu = amus[it], ars = arss[it];
            uint4 o;
            __half* ho = (__half*)&o;
            ho[0] = __float2half(fmaxf((__half2float(hv[0]) - amu) * ars * gg0.x + bb0.x, 0.f));
            ho[1] = __float2half(fmaxf((__half2float(hv[1]) - amu) * ars * gg0.y + bb0.y, 0.f));
            ho[2] = __float2half(fmaxf((__half2float(hv[2]) - amu) * ars * gg0.z + bb0.z, 0.f));
            ho[3] = __float2half(fmaxf((__half2float(hv[3]) - amu) * ars * gg0.w + bb0.w, 0.f));
            ho[4] = __float2half(fmaxf((__half2float(hv[4]) - amu) * ars * gg1.x + bb1.x, 0.f));
            ho[5] = __float2half(fmaxf((__half2float(hv[5]) - amu) * ars * gg1.y + bb1.y, 0.f));
            ho[6] = __float2half(fmaxf((__half2float(hv[6]) - amu) * ars * gg1.z + bb1.z, 0.f));
            ho[7] = __float2half(fmaxf((__half2float(hv[7]) - amu) * ars * gg1.w + bb1.w, 0.f));
            regA[it] = o;
        }
    };
    auto doStsA = [&]() {
        #pragma unroll
        for (int it = 0; it < 4; it++)
            *(uint4*)(sm4 + aSts[it]) = regA[it];
    };
    auto doCpaB = [&](int kc, int st) {
        uint32_t sb = s32 + 16384 + (uint32_t)st * 8192u;
        #pragma unroll
        for (int i = 0; i < 2; i++)
            cpa16(sb + swB[i], g_wch + bofs[i] + kc * 64);
        CP_COMMIT();
    };

    doLoadA(0);
    doCpaB(0, 0);
    int st = 0;

    #pragma unroll 1
    for (int kc = 0; kc < 16; kc++) {
        __syncthreads();
        if (kc < 15) doCpaB(kc + 1, st ^ 1);
        if (kc < 15) { CP_WAIT(1); } else { CP_WAIT(0); }
        doStsA();
        if (kc < 15) doLoadA(kc + 1);
        __syncthreads();

        uint32_t bS = s32 + 16384 + (uint32_t)st * 8192u;
        #pragma unroll
        for (int kt = 0; kt < 4; kt++) {
            uint32_t ah[2][4], bf[2][4];
            #pragma unroll
            for (int mt = 0; mt < 2; mt++) {
                uint32_t cb = ((uint32_t)(kt * 32 + lac2)) ^ aXor[mt];
                ldsm4(ah[mt], s32 + aBase[mt] + cb);
            }
            #pragma unroll
            for (int np = 0; np < 2; np++) {
                uint32_t cb = ((uint32_t)(kt * 32 + lbc2)) ^ bXor[np];
                ldsm4(bf[np], bS + bBase[np] + cb);
            }
            #pragma unroll
            for (int mt = 0; mt < 2; mt++)
                #pragma unroll
                for (int nt = 0; nt < 4; nt++)
                    mma16816h(acc[mt][nt], ah[mt], &bf[nt >> 1][(nt & 1) * 2]);
        }
        st ^= 1;
    }

    #pragma unroll
    for (int mt = 0; mt < 2; mt++) {
        int r = wm * 32 + mt * 16 + (lid >> 2);
        int gr = bx * 128 + r;
        #pragma unroll
        for (int nt = 0; nt < 4; nt++) {
            int c = wn * 32 + nt * 8 + l2 * 2;
            float b0 = bc[c], b1v = bc[c + 1];
            float2 v0 = make_float2(ftanh(acc[mt][nt][0] + b0), ftanh(acc[mt][nt][1] + b1v));
            float2 v1 = make_float2(ftanh(acc[mt][nt][2] + b0), ftanh(acc[mt][nt][3] + b1v));
            *(float2*)(out + (size_t)gr * AA + c) = v0;
            *(float2*)(out + (size_t)(gr + 8) * AA + c) = v1;
        }
    }
}

// ---------------- launch ----------------
extern "C" void kernel_launch(void* const* d_in, const int* in_sizes, int n_in,
                              void* d_out, int out_size) {
    int s = (n_in >= 18) ? 1 : 0;
    const float* ud  = (const float*)d_in[0];
    const int*   au  = (const int*)  d_in[2];
    const float* g1  = (const float*)d_in[3 + s];
    const float* b1  = (const float*)d_in[4 + s];
    const float* Wd  = (const float*)d_in[5 + s];
    const float* bd  = (const float*)d_in[6 + s];
    const float* g2  = (const float*)d_in[7 + s];
    const float* b2  = (const float*)d_in[8 + s];
    const float* Wfw = (const float*)d_in[9 + s];
    const float* bfw = (const float*)d_in[10 + s];
    const float* Wbw = (const float*)d_in[11 + s];
    const float* bbw = (const float*)d_in[12 + s];
    const float* g3  = (const float*)d_in[13 + s];
    const float* b3  = (const float*)d_in[14 + s];
    const float* Wc  = (const float*)d_in[15 + s];
    const float* bc  = (const float*)d_in[16 + s];
    float* out = (float*)d_out;

    const int K2_SMEM = 1024 + 3 * 49152 + 66048 + 17408;   // 231936 bytes
    cudaFuncSetAttribute(k2p_persist, cudaFuncAttributeMaxDynamicSharedMemorySize, K2_SMEM);

    kp_w<<<(2 * KIN * G4) / 256, 256>>>(Wfw, Wbw);
    kp_dc<<<512, 256>>>(Wd, Wc, g1, b1);
    k1_dense<<<BT / 128, 256>>>(ud, g1, bd, g2, b2);
    k2p_persist<<<dim3(16, 4, 2), 256, K2_SMEM>>>(bfw, bbw, au);
    k3f_final<<<BB / 256, 256>>>();
    k4_out<<<BT / 128, 256>>>(g3, b3, bc, out);
}